// round 10
// baseline (speedup 1.0000x reference)
#include <cuda_runtime.h>
#include <cuda_bf16.h>
#include <math.h>
#include <cstdint>

#define NN 20000
#define NE 320000
#define NSLOT (NE + NN)
#define D  128
#define H  12
#define HO 1536          // H * D
#define BN_EPS 1e-5f
#define MPAD 20096       // 157 * 128
#define KTA 256          // [hi|lo] storage, logical K=384 via chunk reuse

// mma smem: rows of 64 bf16 data + 16B pad = 144 B -> LDSM conflict-free
#define ROWB   144
#define BCH    (256 * ROWB)          // 36864 B  (B chunk: 256 rows)
#define ACH    (128 * ROWB)          // 18432 B  (A chunk: 128 rows)
#define SMEM_MMA (4 * BCH + 4 * ACH) // 221184 B

typedef unsigned long long u64;
typedef uint32_t u32;

// ---------------- packed f32x2 helpers --------------------------------------
__device__ __forceinline__ u64 pack2(float lo, float hi) {
    u64 r; asm("mov.b64 %0, {%1,%2};" : "=l"(r) : "f"(lo), "f"(hi)); return r;
}
__device__ __forceinline__ u64 ffma2(u64 a, u64 b, u64 c) {
    u64 d; asm("fma.rn.f32x2 %0, %1, %2, %3;" : "=l"(d) : "l"(a), "l"(b), "l"(c)); return d;
}
__device__ __forceinline__ void unpack2(u64 v, float& lo, float& hi) {
    asm("mov.b64 {%0,%1}, %2;" : "=f"(lo), "=f"(hi) : "l"(v));
}
union F4U { float4 f; u64 u[2]; };

// ---------------- mma building blocks ---------------------------------------
__device__ __forceinline__ u32 smem_u32(const void* p) {
    u32 a;
    asm("{ .reg .u64 t; cvta.to.shared.u64 t, %1; cvt.u32.u64 %0, t; }" : "=r"(a) : "l"(p));
    return a;
}
__device__ __forceinline__ void cp16(u32 saddr, const void* g) {
    asm volatile("cp.async.cg.shared.global [%0], [%1], 16;" :: "r"(saddr), "l"(g));
}
__device__ __forceinline__ void ldsm4(u32& r0, u32& r1, u32& r2, u32& r3, u32 addr) {
    asm volatile("ldmatrix.sync.aligned.m8n8.x4.shared.b16 {%0,%1,%2,%3}, [%4];"
                 : "=r"(r0), "=r"(r1), "=r"(r2), "=r"(r3) : "r"(addr));
}

// ---------------- scratch (device globals) ----------------------------------
__device__ __nv_bfloat16 g_Abig[(size_t)MPAD * KTA];      // [row, 256] = [hi|lo]
__device__ __nv_bfloat16 g_Bbig[(size_t)3 * HO * KTA];    // 3 layers of weights
__device__ float g_Y[(size_t)NN * HO];
__device__ float g_msg[(size_t)NSLOT * D];                // dst-sorted edge messages
__device__ float g_U[NN * H];
__device__ float g_t[NN * D];
__device__ float g_h[NN * D];
__device__ int   g_deg[NN];                                // in-degree incl self
__device__ float g_sum[D];
__device__ float g_sumsq[D];
__device__ int   g_rowptr[NN + 1];    // src-CSR
__device__ int   g_rowptr2[NN + 1];   // dst-CSR (slot ranges in g_msg)
__device__ int   g_cnt[NN];
__device__ int   g_cnt2[NN];
__device__ int   g_adj[NE];           // dst per src-CSR slot
__device__ int   g_pos[NSLOT];        // msg slot per src-CSR slot; self at NE+n

// ---------------- prologue: init / count / scan / fill ----------------------
__global__ void init_kernel() {
    int i = blockIdx.x * blockDim.x + threadIdx.x;
    if (i < NN) { g_deg[i] = 1; g_cnt[i] = 0; }
}
__global__ void count_kernel(const int* __restrict__ ei) {
    int e = blockIdx.x * blockDim.x + threadIdx.x;
    if (e < NE) {
        atomicAdd(&g_cnt[ei[e]], 1);        // out-degree (src)
        atomicAdd(&g_deg[ei[NE + e]], 1);   // in-degree (dst)
    }
}
// scans g_cnt -> g_rowptr (then zeroes g_cnt) and g_deg -> g_rowptr2 (zeroes g_cnt2)
__global__ void scan2_kernel() {
    __shared__ int sh[1024];
    __shared__ int carry;
#pragma unroll
    for (int pass = 0; pass < 2; pass++) {
        const int* src = pass ? g_deg : g_cnt;
        int* dst = pass ? g_rowptr2 : g_rowptr;
        if (threadIdx.x == 0) { carry = 0; dst[0] = 0; }
        __syncthreads();
        for (int base = 0; base < NN; base += 1024) {
            int i = base + threadIdx.x;
            int v = (i < NN) ? src[i] : 0;
            sh[threadIdx.x] = v;
            __syncthreads();
            for (int o = 1; o < 1024; o <<= 1) {
                int t = (threadIdx.x >= o) ? sh[threadIdx.x - o] : 0;
                __syncthreads();
                sh[threadIdx.x] += t;
                __syncthreads();
            }
            int base_off = carry;
            __syncthreads();
            if (i < NN) {
                dst[i + 1] = base_off + sh[threadIdx.x];
                if (pass == 0) g_cnt[i] = 0; else g_cnt2[i] = 0;
            }
            __syncthreads();
            if (threadIdx.x == 0) carry = base_off + sh[1023];
            __syncthreads();
        }
        __syncthreads();
    }
}
// fills src-CSR adj + dst-sorted msg positions; e>=NE handles self loops
__global__ void fill_kernel(const int* __restrict__ ei) {
    int e = blockIdx.x * blockDim.x + threadIdx.x;
    if (e >= NSLOT) return;
    if (e < NE) {
        int s = ei[e], d = ei[NE + e];
        int srcslot = g_rowptr[s] + atomicAdd(&g_cnt[s], 1);
        g_adj[srcslot] = d;
        g_pos[srcslot] = g_rowptr2[d] + atomicAdd(&g_cnt2[d], 1);
    } else {
        int n = e - NE;
        g_pos[e] = g_rowptr2[n] + atomicAdd(&g_cnt2[n], 1);
    }
}

// ---------------- input converts (bf16 double split, [hi|lo]) ---------------
__global__ void convertx_kernel(const float* __restrict__ X) {
    int i = blockIdx.x * blockDim.x + threadIdx.x;
    if (i >= MPAD * D) return;
    int n = i >> 7, c = i & 127;
    float v = (n < NN) ? X[i] : 0.f;
    __nv_bfloat16 hi = __float2bfloat16(v);
    __nv_bfloat16 lo = __float2bfloat16(v - __bfloat162float(hi));
    size_t base = (size_t)n * KTA + c;
    g_Abig[base]       = hi;
    g_Abig[base + 128] = lo;
}
__global__ void bnconvert_kernel(const float* __restrict__ t,
                                 const float* __restrict__ gam,
                                 const float* __restrict__ bet) {
    int i = blockIdx.x * blockDim.x + threadIdx.x;
    if (i >= MPAD * D) return;
    int n = i >> 7, c = i & 127;
    float v = 0.f;
    if (n < NN) {
        const float invN = 1.f / (float)NN;
        float m  = g_sum[c] * invN;
        float vr = g_sumsq[c] * invN - m * m;
        v = (t[i] - m) * rsqrtf(vr + BN_EPS) * gam[c] + bet[c];
        g_h[i] = v;
    }
    __nv_bfloat16 hi = __float2bfloat16(v);
    __nv_bfloat16 lo = __float2bfloat16(v - __bfloat162float(hi));
    size_t base = (size_t)n * KTA + c;
    g_Abig[base]       = hi;
    g_Abig[base + 128] = lo;
}
// all 3 layers' weights at once
__global__ void convertw3_kernel(const float* __restrict__ W0,
                                 const float* __restrict__ W1,
                                 const float* __restrict__ W2) {
    int i = blockIdx.x * blockDim.x + threadIdx.x;
    if (i >= 3 * HO * D) return;
    int l = i / (HO * D);
    int j = i - l * (HO * D);
    const float* W = (l == 0) ? W0 : (l == 1) ? W1 : W2;
    float v = W[j];
    int o = j >> 7, c = j & 127;
    __nv_bfloat16 hi = __float2bfloat16(v);
    __nv_bfloat16 lo = __float2bfloat16(v - __bfloat162float(hi));
    size_t base = (size_t)l * HO * KTA + (size_t)o * KTA + c;
    g_Bbig[base]       = hi;
    g_Bbig[base + 128] = lo;
}

// ---------------- B-resident mma GEMM ---------------------------------------
// grid (6, 24), 512 threads (16 warps, 4x4, warp tile 32x64).
__global__ void __launch_bounds__(512, 1) mma_y_kernel(int layer) {
    extern __shared__ char smem[];
    const u32 sb = smem_u32(smem);
    const int tid = threadIdx.x, wid = tid >> 5, lane = tid & 31;
    const int wm = (wid >> 2) * 32;
    const int wn = (wid & 3) * 64;
    const int bo = blockIdx.x * 256;
    const int g  = lane >> 2, tq = lane & 3;

    const u32 sB = sb;
    const u32 sA = sb + 4 * BCH;
    const __nv_bfloat16* Bbase = g_Bbig + (size_t)layer * HO * KTA;

    const int a_row = wm + (lane & 15);
    const int a_kb  = (lane >> 4) * 16;
    const int b_t   = lane >> 3;
    const int b_row = wn + ((b_t >> 1) * 8) + (lane & 7);
    const int b_kb  = (b_t & 1) * 16;

    {   // load B resident
        const int r = tid >> 1, hb = (tid & 1) * 64;
        const char* gB = (const char*)Bbase + (size_t)(bo + r) * (KTA * 2) + hb;
#pragma unroll
        for (int c = 0; c < 4; c++) {
            u32 dst = sB + c * BCH + r * ROWB + hb;
            const char* src = gB + c * 128;
#pragma unroll
            for (int j = 0; j < 4; j++) cp16(dst + j * 16, src + j * 16);
        }
    }

    const int ar = tid >> 2;
    const int aq = (tid & 3) * 32;
    auto loadA = [&](int buf, int bm, int coff) {
        const char* src = (const char*)g_Abig + (size_t)(bm + ar) * (KTA * 2) + coff + aq;
        u32 dst = sA + buf * ACH + ar * ROWB + aq;
        cp16(dst, src);
        cp16(dst + 16, src + 16);
    };

    const int bm0 = blockIdx.y * 128;
    loadA(0, bm0, 0);
    loadA(1, bm0, 128);
    asm volatile("cp.async.commit_group;");

    float acc[2][8][4];

    auto stepK = [&](u32 Ab, u32 Bb) {
#pragma unroll
        for (int k = 0; k < 4; k++) {
            const int kb = k * 32;
            u32 a[2][4], b[4][4];
#pragma unroll
            for (int i = 0; i < 2; i++)
                ldsm4(a[i][0], a[i][1], a[i][2], a[i][3],
                      Ab + (a_row + i * 16) * ROWB + kb + a_kb);
#pragma unroll
            for (int jj = 0; jj < 4; jj++)
                ldsm4(b[jj][0], b[jj][1], b[jj][2], b[jj][3],
                      Bb + (b_row + jj * 16) * ROWB + kb + b_kb);
#pragma unroll
            for (int i = 0; i < 2; i++)
#pragma unroll
                for (int j = 0; j < 8; j++) {
                    const u32 b0 = b[j >> 1][(j & 1) * 2];
                    const u32 b1 = b[j >> 1][(j & 1) * 2 + 1];
                    asm volatile(
                        "mma.sync.aligned.m16n8k16.row.col.f32.bf16.bf16.f32 "
                        "{%0,%1,%2,%3}, {%4,%5,%6,%7}, {%8,%9}, {%0,%1,%2,%3};"
                        : "+f"(acc[i][j][0]), "+f"(acc[i][j][1]),
                          "+f"(acc[i][j][2]), "+f"(acc[i][j][3])
                        : "r"(a[i][0]), "r"(a[i][1]), "r"(a[i][2]), "r"(a[i][3]),
                          "r"(b0), "r"(b1));
                }
        }
    };

    for (int tmi = blockIdx.y; tmi < 157; tmi += 24) {
        const int bm = tmi * 128;
#pragma unroll
        for (int i = 0; i < 2; i++)
#pragma unroll
            for (int j = 0; j < 8; j++)
#pragma unroll
                for (int q = 0; q < 4; q++) acc[i][j][q] = 0.f;

        __syncthreads();
        loadA(2, bm, 256);
        loadA(3, bm, 384);
        asm volatile("cp.async.commit_group;");
        asm volatile("cp.async.wait_group 1;");
        __syncthreads();

        stepK(sA + 0 * ACH, sB + 0 * BCH);
        stepK(sA + 1 * ACH, sB + 1 * BCH);
        stepK(sA + 0 * ACH, sB + 2 * BCH);
        stepK(sA + 1 * ACH, sB + 3 * BCH);

        __syncthreads();
        const int nt = tmi + 24;
        if (nt < 157) {
            loadA(0, nt * 128, 0);
            loadA(1, nt * 128, 128);
            asm volatile("cp.async.commit_group;");
            asm volatile("cp.async.wait_group 1;");
        } else {
            asm volatile("cp.async.wait_group 0;");
        }
        __syncthreads();

        stepK(sA + 2 * ACH, sB + 0 * BCH);
        stepK(sA + 3 * ACH, sB + 1 * BCH);

#pragma unroll
        for (int i = 0; i < 2; i++) {
            int r0 = bm + wm + i * 16 + g;
            int r1 = r0 + 8;
#pragma unroll
            for (int j = 0; j < 8; j++) {
                int col = bo + wn + j * 8 + tq * 2;
                if (r0 < NN)
                    *(float2*)(g_Y + (size_t)r0 * HO + col) =
                        make_float2(acc[i][j][0], acc[i][j][1]);
                if (r1 < NN)
                    *(float2*)(g_Y + (size_t)r1 * HO + col) =
                        make_float2(acc[i][j][2], acc[i][j][3]);
            }
        }
    }
}

// ---------------- U[n,h] = sum_k X[n,k]*Wu[h,k]  (warp per node) ------------
__global__ void u_kernel(const float* __restrict__ X, const float* __restrict__ Wu, int M) {
    __shared__ float wu[H * D];
    for (int i = threadIdx.x; i < H * D; i += blockDim.x) wu[i] = Wu[i];
    __syncthreads();
    int warp = blockIdx.x * (blockDim.x >> 5) + (threadIdx.x >> 5);
    int lane = threadIdx.x & 31;
    if (warp >= M) return;
    const float* xr = X + (size_t)warp * D;
    float x0 = xr[lane], x1 = xr[lane + 32], x2 = xr[lane + 64], x3 = xr[lane + 96];
#pragma unroll
    for (int h = 0; h < H; h++) {
        float p = x0 * wu[h * D + lane] + x1 * wu[h * D + lane + 32]
                + x2 * wu[h * D + lane + 64] + x3 * wu[h * D + lane + 96];
#pragma unroll
        for (int o = 16; o; o >>= 1) p += __shfl_xor_sync(0xffffffffu, p, o);
        if (lane == 0) g_U[warp * H + h] = p;
    }
}

// ---------------- scatter: warp per SRC node, msg -> unique slot (STG) ------
__global__ __launch_bounds__(256) void scatter_kernel(const float* __restrict__ cvec) {
    // reset BN accumulators for this layer (gather writes them later)
    if (blockIdx.x == 0 && threadIdx.x < D) {
        g_sum[threadIdx.x] = 0.f;
        g_sumsq[threadIdx.x] = 0.f;
    }
    int warp = blockIdx.x * 8 + (threadIdx.x >> 5);
    int lane = threadIdx.x & 31;
    if (warp >= NN) return;
    const int s = warp;

    F4U yv[H];
    const float4* y4 = reinterpret_cast<const float4*>(g_Y + (size_t)s * HO) + lane;
#pragma unroll
    for (int h = 0; h < H; h++) yv[h].f = y4[h * 32];

    float us = 0.f, cl = 0.f;
    if (lane < H) { us = g_U[s * H + lane]; cl = __ldg(&cvec[lane]); }

    int row = g_rowptr[s], end = g_rowptr[s + 1];
    for (int i = row - 1; i < end; i++) {     // i == row-1 encodes the self loop
        int d = s, pos;
        float ud = us;
        if (i >= row) {
            d = g_adj[i];
            pos = g_pos[i];
            ud = (lane < H) ? __ldg(&g_U[d * H + lane]) : 0.f;
        } else {
            pos = g_pos[NE + s];
        }
        float logit = (lane < H) ? (ud - us + cl) : -1e30f;
        float m = logit;
#pragma unroll
        for (int o = 16; o; o >>= 1) m = fmaxf(m, __shfl_xor_sync(0xffffffffu, m, o));
        float e = (lane < H) ? __expf(logit - m) : 0.f;
        float ss = e;
#pragma unroll
        for (int o = 16; o; o >>= 1) ss += __shfl_xor_sync(0xffffffffu, ss, o);
        float a = e / ss;

        u64 m0 = 0ull, m1 = 0ull;
#pragma unroll
        for (int h = 0; h < H; h++) {
            float ah = __shfl_sync(0xffffffffu, a, h);
            u64 a2 = pack2(ah, ah);
            m0 = ffma2(a2, yv[h].u[0], m0);
            m1 = ffma2(a2, yv[h].u[1], m1);
        }
        float r0, r1, r2, r3;
        unpack2(m0, r0, r1);
        unpack2(m1, r2, r3);
        *(float4*)(g_msg + (size_t)pos * D + lane * 4) = make_float4(r0, r1, r2, r3);
    }
}

// ---------------- gather + finalize: warp per DST, sequential reads ---------
__global__ __launch_bounds__(256) void gather_kernel(const float* __restrict__ bvec,
                                                     float* __restrict__ out,
                                                     int relu, int do_stats) {
    const int lane = threadIdx.x & 31;
    const int gw = (blockIdx.x * 256 + threadIdx.x) >> 5;
    const int NWARP = 192 * 8;
    float4 b4 = ((const float4*)bvec)[lane];
    float4 lsum = make_float4(0.f, 0.f, 0.f, 0.f);
    float4 lsq  = make_float4(0.f, 0.f, 0.f, 0.f);

    for (int d = gw; d < NN; d += NWARP) {
        int base = g_rowptr2[d];
        int cnt  = g_rowptr2[d + 1] - base;
        float4 sm = make_float4(0.f, 0.f, 0.f, 0.f);
        const float4* mp = (const float4*)g_msg + (size_t)base * 32 + lane;
        for (int k = 0; k < cnt; k++) {
            float4 v = mp[(size_t)k * 32];
            sm.x += v.x; sm.y += v.y; sm.z += v.z; sm.w += v.w;
        }
        float inv = 1.f / (float)cnt;
        float4 o;
        o.x = sm.x * inv + b4.x; o.y = sm.y * inv + b4.y;
        o.z = sm.z * inv + b4.z; o.w = sm.w * inv + b4.w;
        if (relu) {
            o.x = fmaxf(o.x, 0.f); o.y = fmaxf(o.y, 0.f);
            o.z = fmaxf(o.z, 0.f); o.w = fmaxf(o.w, 0.f);
        }
        ((float4*)out)[(size_t)d * 32 + lane] = o;
        lsum.x += o.x; lsum.y += o.y; lsum.z += o.z; lsum.w += o.w;
        lsq.x += o.x * o.x; lsq.y += o.y * o.y;
        lsq.z += o.z * o.z; lsq.w += o.w * o.w;
    }

    if (do_stats) {
        __shared__ float4 s1[256], s2[256];
        s1[threadIdx.x] = lsum; s2[threadIdx.x] = lsq;
        __syncthreads();
        if (threadIdx.x < 32) {
            float4 a = s1[threadIdx.x], b = s2[threadIdx.x];
#pragma unroll
            for (int w = 1; w < 8; w++) {
                float4 t1 = s1[threadIdx.x + w * 32], t2 = s2[threadIdx.x + w * 32];
                a.x += t1.x; a.y += t1.y; a.z += t1.z; a.w += t1.w;
                b.x += t2.x; b.y += t2.y; b.z += t2.z; b.w += t2.w;
            }
            int c = threadIdx.x * 4;
            atomicAdd(&g_sum[c + 0], a.x); atomicAdd(&g_sum[c + 1], a.y);
            atomicAdd(&g_sum[c + 2], a.z); atomicAdd(&g_sum[c + 3], a.w);
            atomicAdd(&g_sumsq[c + 0], b.x); atomicAdd(&g_sumsq[c + 1], b.y);
            atomicAdd(&g_sumsq[c + 2], b.z); atomicAdd(&g_sumsq[c + 3], b.w);
        }
    }
}

// ---------------- launch ----------------------------------------------------
static void launch_mma(int layer) {
    cudaFuncSetAttribute(mma_y_kernel, cudaFuncAttributeMaxDynamicSharedMemorySize, SMEM_MMA);
    mma_y_kernel<<<dim3(6, 24), 512, SMEM_MMA>>>(layer);
}

extern "C" void kernel_launch(void* const* d_in, const int* in_sizes, int n_in,
                              void* d_out, int out_size)
{
    const float* x  = (const float*)d_in[0];
    const int*   ei = (const int*)d_in[1];

    const float *Wlin[3], *Wu[3], *cv[3], *bv[3], *bng[2], *bnb[2];
    if (in_sizes[6] == H * D * D) {
        for (int l = 0; l < 3; l++) {
            Wlin[l] = (const float*)d_in[2 + 4 * l];
            Wu[l]   = (const float*)d_in[3 + 4 * l];
            cv[l]   = (const float*)d_in[4 + 4 * l];
            bv[l]   = (const float*)d_in[5 + 4 * l];
        }
        bng[0] = (const float*)d_in[14]; bnb[0] = (const float*)d_in[15];
        bng[1] = (const float*)d_in[16]; bnb[1] = (const float*)d_in[17];
    } else {
        Wlin[0] = (const float*)d_in[2];  Wu[0] = (const float*)d_in[3];
        cv[0]   = (const float*)d_in[4];  bv[0] = (const float*)d_in[5];
        bng[0]  = (const float*)d_in[6];  bnb[0] = (const float*)d_in[7];
        Wlin[1] = (const float*)d_in[8];  Wu[1] = (const float*)d_in[9];
        cv[1]   = (const float*)d_in[10]; bv[1] = (const float*)d_in[11];
        bng[1]  = (const float*)d_in[12]; bnb[1] = (const float*)d_in[13];
        Wlin[2] = (const float*)d_in[14]; Wu[2] = (const float*)d_in[15];
        cv[2]   = (const float*)d_in[16]; bv[2] = (const float*)d_in[17];
    }

    float* out = (float*)d_out;
    float* t = nullptr; float* hbuf = nullptr;
    cudaGetSymbolAddress((void**)&t, g_t);
    cudaGetSymbolAddress((void**)&hbuf, g_h);

    const int NCONV = (MPAD * D + 255) / 256;

    // ---- layer 0 front (launch index 3 == mma_y for the ncu -s window) ----
    convertx_kernel<<<NCONV, 256>>>(x);                               // 0
    convertw3_kernel<<<(3 * HO * D + 255) / 256, 256>>>(Wlin[0], Wlin[1], Wlin[2]); // 1
    init_kernel<<<(NN + 255) / 256, 256>>>();                         // 2
    launch_mma(0);                                                    // 3 <- profiled
    count_kernel<<<(NE + 255) / 256, 256>>>(ei);
    scan2_kernel<<<1, 1024>>>();
    fill_kernel<<<(NSLOT + 255) / 256, 256>>>(ei);
    u_kernel<<<(NN * 32 + 255) / 256, 256>>>(x, Wu[0], NN);
    scatter_kernel<<<(NN + 7) / 8, 256>>>(cv[0]);
    gather_kernel<<<192, 256>>>(bv[0], t, 1, 1);

    // ---- layer 1 ----
    bnconvert_kernel<<<NCONV, 256>>>(t, bng[0], bnb[0]);
    launch_mma(1);
    u_kernel<<<(NN * 32 + 255) / 256, 256>>>(hbuf, Wu[1], NN);
    scatter_kernel<<<(NN + 7) / 8, 256>>>(cv[1]);
    gather_kernel<<<192, 256>>>(bv[1], t, 1, 1);

    // ---- layer 2 -> d_out ----
    bnconvert_kernel<<<NCONV, 256>>>(t, bng[1], bnb[1]);
    launch_mma(2);
    u_kernel<<<(NN * 32 + 255) / 256, 256>>>(hbuf, Wu[2], NN);
    scatter_kernel<<<(NN + 7) / 8, 256>>>(cv[2]);
    gather_kernel<<<192, 256>>>(bv[2], out, 0, 0);
}

// round 11
// speedup vs baseline: 1.1621x; 1.1621x over previous
#include <cuda_runtime.h>
#include <cuda_bf16.h>
#include <math.h>
#include <cstdint>

#define NN 20000
#define NE 320000
#define D  128
#define H  12
#define HO 1536          // H * D
#define BN_EPS 1e-5f
#define MPAD 20096       // 314 * 64
#define KTA 256          // [hi|lo] storage, logical K=384 via chunk reuse
#define MTILES 314       // MPAD / 64

// mma smem: rows of 64 bf16 data + 16B pad = 144 B -> LDSM conflict-free
#define ROWB   144
#define BCH    (128 * ROWB)          // 18432 B  (B chunk: 128 rows)
#define ACH    (64 * ROWB)           // 9216 B   (A chunk: 64 rows)
#define SMEM_MMA (4 * BCH + 4 * ACH) // 110592 B -> 2 CTAs/SM

typedef unsigned long long u64;
typedef uint32_t u32;

// ---------------- packed f32x2 helpers --------------------------------------
__device__ __forceinline__ u64 pack2(float lo, float hi) {
    u64 r; asm("mov.b64 %0, {%1,%2};" : "=l"(r) : "f"(lo), "f"(hi)); return r;
}
__device__ __forceinline__ u64 ffma2(u64 a, u64 b, u64 c) {
    u64 d; asm("fma.rn.f32x2 %0, %1, %2, %3;" : "=l"(d) : "l"(a), "l"(b), "l"(c)); return d;
}
__device__ __forceinline__ void unpack2(u64 v, float& lo, float& hi) {
    asm("mov.b64 {%0,%1}, %2;" : "=f"(lo), "=f"(hi) : "l"(v));
}
__device__ __forceinline__ void red_add_v4(float* p, float a, float b, float c, float d) {
    asm volatile("red.global.add.v4.f32 [%0], {%1,%2,%3,%4};"
                 :: "l"(p), "f"(a), "f"(b), "f"(c), "f"(d) : "memory");
}
union F4U { float4 f; u64 u[2]; };

// ---------------- mma building blocks ---------------------------------------
__device__ __forceinline__ u32 smem_u32(const void* p) {
    u32 a;
    asm("{ .reg .u64 t; cvta.to.shared.u64 t, %1; cvt.u32.u64 %0, t; }" : "=r"(a) : "l"(p));
    return a;
}
__device__ __forceinline__ void cp16(u32 saddr, const void* g) {
    asm volatile("cp.async.cg.shared.global [%0], [%1], 16;" :: "r"(saddr), "l"(g));
}
__device__ __forceinline__ void ldsm4(u32& r0, u32& r1, u32& r2, u32& r3, u32 addr) {
    asm volatile("ldmatrix.sync.aligned.m8n8.x4.shared.b16 {%0,%1,%2,%3}, [%4];"
                 : "=r"(r0), "=r"(r1), "=r"(r2), "=r"(r3) : "r"(addr));
}

// ---------------- scratch (device globals) ----------------------------------
__device__ __nv_bfloat16 g_Abig[(size_t)MPAD * KTA];      // [row, 256] = [hi|lo]
__device__ __nv_bfloat16 g_Bbig[(size_t)3 * HO * KTA];    // 3 layers of weights
__device__ float g_Y[(size_t)NN * HO];
__device__ float g_U[NN * H];
__device__ float g_t[NN * D];
__device__ float g_h[NN * D];
__device__ float g_agg[NN * D];
__device__ int   g_deg[NN];           // in-degree incl self
__device__ float g_sum[D];
__device__ float g_sumsq[D];
__device__ int   g_rowptr[NN + 1];    // src-CSR
__device__ int   g_cnt[NN];
__device__ int   g_adj[NE];

// ---------------- prologue ---------------------------------------------------
__global__ void init_kernel() {
    int i = blockIdx.x * blockDim.x + threadIdx.x;
    if (i < NN) { g_deg[i] = 1; g_cnt[i] = 0; }
}
__global__ void count_kernel(const int* __restrict__ ei) {
    int e = blockIdx.x * blockDim.x + threadIdx.x;
    if (e < NE) {
        atomicAdd(&g_cnt[ei[e]], 1);        // out-degree (src)
        atomicAdd(&g_deg[ei[NE + e]], 1);   // in-degree (dst)
    }
}
__global__ void scan_kernel() {
    __shared__ int sh[1024];
    __shared__ int carry;
    if (threadIdx.x == 0) { carry = 0; g_rowptr[0] = 0; }
    __syncthreads();
    for (int base = 0; base < NN; base += 1024) {
        int i = base + threadIdx.x;
        int v = (i < NN) ? g_cnt[i] : 0;
        sh[threadIdx.x] = v;
        __syncthreads();
        for (int o = 1; o < 1024; o <<= 1) {
            int t = (threadIdx.x >= o) ? sh[threadIdx.x - o] : 0;
            __syncthreads();
            sh[threadIdx.x] += t;
            __syncthreads();
        }
        int base_off = carry;
        __syncthreads();
        if (i < NN) { g_rowptr[i + 1] = base_off + sh[threadIdx.x]; g_cnt[i] = 0; }
        __syncthreads();
        if (threadIdx.x == 0) carry = base_off + sh[1023];
        __syncthreads();
    }
}
__global__ void fill_kernel(const int* __restrict__ ei) {
    int e = blockIdx.x * blockDim.x + threadIdx.x;
    if (e >= NE) return;
    int s = ei[e];
    int pos = atomicAdd(&g_cnt[s], 1);
    g_adj[g_rowptr[s] + pos] = ei[NE + e];
}

// ---------------- input converts (bf16 double split, [hi|lo]) ---------------
__global__ void convertx_kernel(const float* __restrict__ X) {
    int i = blockIdx.x * blockDim.x + threadIdx.x;
    if (i >= MPAD * D) return;
    int n = i >> 7, c = i & 127;
    float v = (n < NN) ? X[i] : 0.f;
    __nv_bfloat16 hi = __float2bfloat16(v);
    __nv_bfloat16 lo = __float2bfloat16(v - __bfloat162float(hi));
    size_t base = (size_t)n * KTA + c;
    g_Abig[base]       = hi;
    g_Abig[base + 128] = lo;
}
__global__ void bnconvert_kernel(const float* __restrict__ t,
                                 const float* __restrict__ gam,
                                 const float* __restrict__ bet) {
    int i = blockIdx.x * blockDim.x + threadIdx.x;
    if (i >= MPAD * D) return;
    int n = i >> 7, c = i & 127;
    float v = 0.f;
    if (n < NN) {
        const float invN = 1.f / (float)NN;
        float m  = g_sum[c] * invN;
        float vr = g_sumsq[c] * invN - m * m;
        v = (t[i] - m) * rsqrtf(vr + BN_EPS) * gam[c] + bet[c];
        g_h[i] = v;
    }
    __nv_bfloat16 hi = __float2bfloat16(v);
    __nv_bfloat16 lo = __float2bfloat16(v - __bfloat162float(hi));
    size_t base = (size_t)n * KTA + c;
    g_Abig[base]       = hi;
    g_Abig[base + 128] = lo;
}
__global__ void convertw3_kernel(const float* __restrict__ W0,
                                 const float* __restrict__ W1,
                                 const float* __restrict__ W2) {
    int i = blockIdx.x * blockDim.x + threadIdx.x;
    if (i >= 3 * HO * D) return;
    int l = i / (HO * D);
    int j = i - l * (HO * D);
    const float* W = (l == 0) ? W0 : (l == 1) ? W1 : W2;
    float v = W[j];
    int o = j >> 7, c = j & 127;
    __nv_bfloat16 hi = __float2bfloat16(v);
    __nv_bfloat16 lo = __float2bfloat16(v - __bfloat162float(hi));
    size_t base = (size_t)l * HO * KTA + (size_t)o * KTA + c;
    g_Bbig[base]       = hi;
    g_Bbig[base + 128] = lo;
}

// ---------------- B-resident mma GEMM (2 CTAs/SM) ----------------------------
// grid (12, 24), 256 threads (8 warps, 2x4, warp tile 32x32).
// CTA tile M=64, N=128; B (4 chunks of K64, 128 rows) resident in smem;
// sweeps M-tiles of 64 rows with stride 24. K-schedule (3-term split, K=384):
//   step: 0     1     2     3     4     5
//   A  :  hi0   hi1   hi0   hi1   lo0   lo1     (buffers 0,1,0,1,2,3)
//   B  :  hi0   hi1   lo0   lo1   hi0   hi1     (chunks  0,1,2,3,0,1)
__global__ void __launch_bounds__(256, 2) mma_y_kernel(int layer) {
    extern __shared__ char smem[];
    const u32 sb = smem_u32(smem);
    const int tid = threadIdx.x, wid = tid >> 5, lane = tid & 31;
    const int wm = (wid >> 2) * 32;
    const int wn = (wid & 3) * 32;
    const int bo = blockIdx.x * 128;
    const int g  = lane >> 2, tq = lane & 3;

    const u32 sB = sb;
    const u32 sA = sb + 4 * BCH;
    const __nv_bfloat16* Bbase = g_Bbig + (size_t)layer * HO * KTA;

    const int a_row = wm + (lane & 15);
    const int a_kb  = (lane >> 4) * 16;
    const int b_t   = lane >> 3;
    const int b_row = wn + ((b_t >> 1) * 8) + (lane & 7);
    const int b_kb  = (b_t & 1) * 16;

    {   // load B resident: 4 chunks x 128 rows x 128 B
        const int r = tid >> 1, hb = (tid & 1) * 64;
        const char* gB = (const char*)Bbase + (size_t)(bo + r) * (KTA * 2) + hb;
#pragma unroll
        for (int c = 0; c < 4; c++) {
            u32 dst = sB + c * BCH + r * ROWB + hb;
            const char* src = gB + c * 128;
#pragma unroll
            for (int j = 0; j < 4; j++) cp16(dst + j * 16, src + j * 16);
        }
    }

    // A loader: 64 rows, 4 threads/row, 2 cp16 each
    const int ar = tid >> 2;
    const int aq = (tid & 3) * 32;
    auto loadA = [&](int buf, int bm, int coff) {
        const char* src = (const char*)g_Abig + (size_t)(bm + ar) * (KTA * 2) + coff + aq;
        u32 dst = sA + buf * ACH + ar * ROWB + aq;
        cp16(dst, src);
        cp16(dst + 16, src + 16);
    };

    const int bm0 = blockIdx.y * 64;
    loadA(0, bm0, 0);
    loadA(1, bm0, 128);
    asm volatile("cp.async.commit_group;");

    float acc[2][4][4];

    auto stepK = [&](u32 Ab, u32 Bb) {
#pragma unroll
        for (int k = 0; k < 4; k++) {
            const int kb = k * 32;
            u32 a[2][4], b[2][4];
#pragma unroll
            for (int i = 0; i < 2; i++)
                ldsm4(a[i][0], a[i][1], a[i][2], a[i][3],
                      Ab + (a_row + i * 16) * ROWB + kb + a_kb);
#pragma unroll
            for (int jj = 0; jj < 2; jj++)
                ldsm4(b[jj][0], b[jj][1], b[jj][2], b[jj][3],
                      Bb + (b_row + jj * 16) * ROWB + kb + b_kb);
#pragma unroll
            for (int i = 0; i < 2; i++)
#pragma unroll
                for (int j = 0; j < 4; j++) {
                    const u32 b0 = b[j >> 1][(j & 1) * 2];
                    const u32 b1 = b[j >> 1][(j & 1) * 2 + 1];
                    asm volatile(
                        "mma.sync.aligned.m16n8k16.row.col.f32.bf16.bf16.f32 "
                        "{%0,%1,%2,%3}, {%4,%5,%6,%7}, {%8,%9}, {%0,%1,%2,%3};"
                        : "+f"(acc[i][j][0]), "+f"(acc[i][j][1]),
                          "+f"(acc[i][j][2]), "+f"(acc[i][j][3])
                        : "r"(a[i][0]), "r"(a[i][1]), "r"(a[i][2]), "r"(a[i][3]),
                          "r"(b0), "r"(b1));
                }
        }
    };

    for (int tmi = blockIdx.y; tmi < MTILES; tmi += 24) {
        const int bm = tmi * 64;
#pragma unroll
        for (int i = 0; i < 2; i++)
#pragma unroll
            for (int j = 0; j < 4; j++)
#pragma unroll
                for (int q = 0; q < 4; q++) acc[i][j][q] = 0.f;

        __syncthreads();                          // lo buffers free of prev readers
        loadA(2, bm, 256);                        // stream lo(t)
        loadA(3, bm, 384);
        asm volatile("cp.async.commit_group;");
        asm volatile("cp.async.wait_group 1;");   // hi(t) (+B on first iter) ready
        __syncthreads();

        stepK(sA + 0 * ACH, sB + 0 * BCH);        // hi0 x B_hi0
        stepK(sA + 1 * ACH, sB + 1 * BCH);        // hi1 x B_hi1
        stepK(sA + 0 * ACH, sB + 2 * BCH);        // hi0 x B_lo0
        stepK(sA + 1 * ACH, sB + 3 * BCH);        // hi1 x B_lo1

        __syncthreads();                          // hi reads complete
        const int nt = tmi + 24;
        if (nt < MTILES) {
            loadA(0, nt * 64, 0);                 // prefetch hi(t+1)
            loadA(1, nt * 64, 128);
            asm volatile("cp.async.commit_group;");
            asm volatile("cp.async.wait_group 1;"); // lo(t) ready
        } else {
            asm volatile("cp.async.wait_group 0;");
        }
        __syncthreads();

        stepK(sA + 2 * ACH, sB + 0 * BCH);        // lo0 x B_hi0
        stepK(sA + 3 * ACH, sB + 1 * BCH);        // lo1 x B_hi1

        // epilogue
#pragma unroll
        for (int i = 0; i < 2; i++) {
            int r0 = bm + wm + i * 16 + g;
            int r1 = r0 + 8;
#pragma unroll
            for (int j = 0; j < 4; j++) {
                int col = bo + wn + j * 8 + tq * 2;
                if (r0 < NN)
                    *(float2*)(g_Y + (size_t)r0 * HO + col) =
                        make_float2(acc[i][j][0], acc[i][j][1]);
                if (r1 < NN)
                    *(float2*)(g_Y + (size_t)r1 * HO + col) =
                        make_float2(acc[i][j][2], acc[i][j][3]);
            }
        }
    }
}

// ---------------- U kernel (+ fused agg/bn-accumulator zeroing) -------------
__global__ void u_kernel(const float* __restrict__ X, const float* __restrict__ Wu) {
    // zero g_agg (exactly NN*D/4 float4 slots == 2500*256 threads)
    {
        int idx = blockIdx.x * blockDim.x + threadIdx.x;
        if (idx < NN * 32) ((float4*)g_agg)[idx] = make_float4(0.f, 0.f, 0.f, 0.f);
        if (blockIdx.x == 0 && threadIdx.x < D) {
            g_sum[threadIdx.x] = 0.f;
            g_sumsq[threadIdx.x] = 0.f;
        }
    }
    __shared__ float wu[H * D];
    for (int i = threadIdx.x; i < H * D; i += blockDim.x) wu[i] = Wu[i];
    __syncthreads();
    int warp = blockIdx.x * (blockDim.x >> 5) + (threadIdx.x >> 5);
    int lane = threadIdx.x & 31;
    if (warp >= NN) return;
    const float* xr = X + (size_t)warp * D;
    float x0 = xr[lane], x1 = xr[lane + 32], x2 = xr[lane + 64], x3 = xr[lane + 96];
#pragma unroll
    for (int h = 0; h < H; h++) {
        float p = x0 * wu[h * D + lane] + x1 * wu[h * D + lane + 32]
                + x2 * wu[h * D + lane + 64] + x3 * wu[h * D + lane + 96];
#pragma unroll
        for (int o = 16; o; o >>= 1) p += __shfl_xor_sync(0xffffffffu, p, o);
        if (lane == 0) g_U[warp * H + h] = p;
    }
}

// ---------------- scatter: warp per SRC node, Y row in registers ------------
__global__ __launch_bounds__(256) void scatter_kernel(const float* __restrict__ cvec) {
    int warp = blockIdx.x * 8 + (threadIdx.x >> 5);
    int lane = threadIdx.x & 31;
    if (warp >= NN) return;
    const int s = warp;

    F4U yv[H];
    const float4* y4 = reinterpret_cast<const float4*>(g_Y + (size_t)s * HO) + lane;
#pragma unroll
    for (int h = 0; h < H; h++) yv[h].f = y4[h * 32];

    float us = 0.f, cl = 0.f;
    if (lane < H) { us = g_U[s * H + lane]; cl = __ldg(&cvec[lane]); }

    int row = g_rowptr[s], end = g_rowptr[s + 1];
    for (int i = row - 1; i < end; i++) {     // i == row-1 encodes the self loop
        int d = s;
        float ud = us;
        if (i >= row) {
            d = g_adj[i];
            ud = (lane < H) ? __ldg(&g_U[d * H + lane]) : 0.f;
        }
        float logit = (lane < H) ? (ud - us + cl) : -1e30f;
        float m = logit;
#pragma unroll
        for (int o = 16; o; o >>= 1) m = fmaxf(m, __shfl_xor_sync(0xffffffffu, m, o));
        float e = (lane < H) ? __expf(logit - m) : 0.f;
        float ss = e;
#pragma unroll
        for (int o = 16; o; o >>= 1) ss += __shfl_xor_sync(0xffffffffu, ss, o);
        float a = e / ss;

        u64 m0 = 0ull, m1 = 0ull;
#pragma unroll
        for (int h = 0; h < H; h++) {
            float ah = __shfl_sync(0xffffffffu, a, h);
            u64 a2 = pack2(ah, ah);
            m0 = ffma2(a2, yv[h].u[0], m0);
            m1 = ffma2(a2, yv[h].u[1], m1);
        }
        float r0, r1, r2, r3;
        unpack2(m0, r0, r1);
        unpack2(m1, r2, r3);
        red_add_v4(g_agg + (size_t)d * D + lane * 4, r0, r1, r2, r3);
    }
}

// ---------------- finalize: out = agg/deg + b (+relu, + BN stats) -----------
__global__ __launch_bounds__(256) void finalize_kernel(const float* __restrict__ bvec,
                                                       float* __restrict__ out,
                                                       int relu, int do_stats) {
    int c = threadIdx.x & 127;
    float bb = __ldg(&bvec[c]);
    float lsum = 0.f, lsq = 0.f;
    for (int i = blockIdx.x * blockDim.x + threadIdx.x; i < NN * D;
         i += gridDim.x * blockDim.x) {
        float v = g_agg[i] / (float)g_deg[i >> 7] + bb;
        if (relu) v = fmaxf(v, 0.f);
        out[i] = v;
        lsum += v; lsq += v * v;
    }
    if (do_stats) {
        __shared__ float s1[256], s2[256];
        s1[threadIdx.x] = lsum; s2[threadIdx.x] = lsq;
        __syncthreads();
        if (threadIdx.x < 128) {
            atomicAdd(&g_sum[threadIdx.x],   s1[threadIdx.x] + s1[threadIdx.x + 128]);
            atomicAdd(&g_sumsq[threadIdx.x], s2[threadIdx.x] + s2[threadIdx.x + 128]);
        }
    }
}

// ---------------- launch ----------------------------------------------------
static void launch_mma(int layer) {
    cudaFuncSetAttribute(mma_y_kernel, cudaFuncAttributeMaxDynamicSharedMemorySize, SMEM_MMA);
    mma_y_kernel<<<dim3(12, 24), 256, SMEM_MMA>>>(layer);
}

extern "C" void kernel_launch(void* const* d_in, const int* in_sizes, int n_in,
                              void* d_out, int out_size)
{
    const float* x  = (const float*)d_in[0];
    const int*   ei = (const int*)d_in[1];

    const float *Wlin[3], *Wu[3], *cv[3], *bv[3], *bng[2], *bnb[2];
    if (in_sizes[6] == H * D * D) {
        for (int l = 0; l < 3; l++) {
            Wlin[l] = (const float*)d_in[2 + 4 * l];
            Wu[l]   = (const float*)d_in[3 + 4 * l];
            cv[l]   = (const float*)d_in[4 + 4 * l];
            bv[l]   = (const float*)d_in[5 + 4 * l];
        }
        bng[0] = (const float*)d_in[14]; bnb[0] = (const float*)d_in[15];
        bng[1] = (const float*)d_in[16]; bnb[1] = (const float*)d_in[17];
    } else {
        Wlin[0] = (const float*)d_in[2];  Wu[0] = (const float*)d_in[3];
        cv[0]   = (const float*)d_in[4];  bv[0] = (const float*)d_in[5];
        bng[0]  = (const float*)d_in[6];  bnb[0] = (const float*)d_in[7];
        Wlin[1] = (const float*)d_in[8];  Wu[1] = (const float*)d_in[9];
        cv[1]   = (const float*)d_in[10]; bv[1] = (const float*)d_in[11];
        bng[1]  = (const float*)d_in[12]; bnb[1] = (const float*)d_in[13];
        Wlin[2] = (const float*)d_in[14]; Wu[2] = (const float*)d_in[15];
        cv[2]   = (const float*)d_in[16]; bv[2] = (const float*)d_in[17];
    }

    float* out = (float*)d_out;
    float* t = nullptr; float* hbuf = nullptr;
    cudaGetSymbolAddress((void**)&t, g_t);
    cudaGetSymbolAddress((void**)&hbuf, g_h);

    const int NCONV = (MPAD * D + 255) / 256;

    // ---- layer 0 front (launch index 3 == mma_y for the ncu -s window) ----
    convertx_kernel<<<NCONV, 256>>>(x);                               // 0
    convertw3_kernel<<<(3 * HO * D + 255) / 256, 256>>>(Wlin[0], Wlin[1], Wlin[2]); // 1
    init_kernel<<<(NN + 255) / 256, 256>>>();                         // 2
    launch_mma(0);                                                    // 3 <- profiled
    count_kernel<<<(NE + 255) / 256, 256>>>(ei);
    scan_kernel<<<1, 1024>>>();
    fill_kernel<<<(NE + 255) / 256, 256>>>(ei);
    u_kernel<<<2500, 256>>>(x, Wu[0]);
    scatter_kernel<<<(NN + 7) / 8, 256>>>(cv[0]);
    finalize_kernel<<<192, 256>>>(bv[0], t, 1, 1);

    // ---- layer 1 ----
    bnconvert_kernel<<<NCONV, 256>>>(t, bng[0], bnb[0]);
    launch_mma(1);
    u_kernel<<<2500, 256>>>(hbuf, Wu[1]);
    scatter_kernel<<<(NN + 7) / 8, 256>>>(cv[1]);
    finalize_kernel<<<192, 256>>>(bv[1], t, 1, 1);

    // ---- layer 2 -> d_out ----
    bnconvert_kernel<<<NCONV, 256>>>(t, bng[1], bnb[1]);
    launch_mma(2);
    u_kernel<<<2500, 256>>>(hbuf, Wu[2]);
    scatter_kernel<<<(NN + 7) / 8, 256>>>(cv[2]);
    finalize_kernel<<<192, 256>>>(bv[2], out, 0, 0);
}

// round 13
// speedup vs baseline: 1.1835x; 1.0184x over previous
#include <cuda_runtime.h>
#include <cuda_bf16.h>
#include <math.h>
#include <cstdint>

#define NN 20000
#define NE 320000
#define D  128
#define H  12
#define HO 1536          // H * D
#define BN_EPS 1e-5f
#define MPAD 20096       // 314 * 64
#define KTA 256          // [hi|lo] storage, logical K=384 via chunk reuse
#define MTILES 314       // MPAD / 64

// mma smem: rows of 64 bf16 data + 16B pad = 144 B -> LDSM conflict-free
#define ROWB   144
#define BCH    (128 * ROWB)          // 18432 B  (B chunk: 128 rows)
#define ACH    (64 * ROWB)           // 9216 B   (A chunk: 64 rows)
#define SMEM_MMA (4 * BCH + 4 * ACH) // 110592 B -> 2 CTAs/SM

typedef unsigned long long u64;
typedef uint32_t u32;

// ---------------- packed f32x2 helpers --------------------------------------
__device__ __forceinline__ u64 pack2(float lo, float hi) {
    u64 r; asm("mov.b64 %0, {%1,%2};" : "=l"(r) : "f"(lo), "f"(hi)); return r;
}
__device__ __forceinline__ u64 ffma2(u64 a, u64 b, u64 c) {
    u64 d; asm("fma.rn.f32x2 %0, %1, %2, %3;" : "=l"(d) : "l"(a), "l"(b), "l"(c)); return d;
}
__device__ __forceinline__ void unpack2(u64 v, float& lo, float& hi) {
    asm("mov.b64 {%0,%1}, %2;" : "=f"(lo), "=f"(hi) : "l"(v));
}
__device__ __forceinline__ void red_add_v4(float* p, float a, float b, float c, float d) {
    asm volatile("red.global.add.v4.f32 [%0], {%1,%2,%3,%4};"
                 :: "l"(p), "f"(a), "f"(b), "f"(c), "f"(d) : "memory");
}
union F4U { float4 f; u64 u[2]; };

// ---------------- mma building blocks ---------------------------------------
__device__ __forceinline__ u32 smem_u32(const void* p) {
    u32 a;
    asm("{ .reg .u64 t; cvta.to.shared.u64 t, %1; cvt.u32.u64 %0, t; }" : "=r"(a) : "l"(p));
    return a;
}
__device__ __forceinline__ void cp16(u32 saddr, const void* g) {
    asm volatile("cp.async.cg.shared.global [%0], [%1], 16;" :: "r"(saddr), "l"(g));
}
__device__ __forceinline__ void ldsm4(u32& r0, u32& r1, u32& r2, u32& r3, u32 addr) {
    asm volatile("ldmatrix.sync.aligned.m8n8.x4.shared.b16 {%0,%1,%2,%3}, [%4];"
                 : "=r"(r0), "=r"(r1), "=r"(r2), "=r"(r3) : "r"(addr));
}

// ---------------- scratch (device globals) ----------------------------------
__device__ __nv_bfloat16 g_Abig[(size_t)MPAD * KTA];      // [row, 256] = [hi|lo]
__device__ __nv_bfloat16 g_Bbig[(size_t)3 * HO * KTA];    // 3 layers of weights
__device__ float g_Y[(size_t)NN * HO];
__device__ float g_U[NN * H];
__device__ float g_t[NN * D];
__device__ float g_agg[NN * D];
__device__ int   g_deg[NN];           // in-degree incl self
__device__ float g_sum[2][D];
__device__ float g_sumsq[2][D];
__device__ int   g_rowptr[NN + 1];    // src-CSR
__device__ int   g_cnt[NN];
__device__ int   g_adj[NE];

// ---------------- prologue ---------------------------------------------------
__global__ void init_kernel() {
    int i = blockIdx.x * blockDim.x + threadIdx.x;
    if (i < NN) { g_deg[i] = 1; g_cnt[i] = 0; }
    if (i < D) {
        g_sum[0][i] = 0.f; g_sum[1][i] = 0.f;
        g_sumsq[0][i] = 0.f; g_sumsq[1][i] = 0.f;
    }
    // zero the padded tail rows of g_Abig (rows NN..MPAD-1), 96 rows * 128 u32
    if (i < (MPAD - NN) * 128) {
        ((u32*)g_Abig)[(size_t)NN * 128 + i] = 0;
    }
}
__global__ void count_kernel(const int* __restrict__ ei) {
    int e = blockIdx.x * blockDim.x + threadIdx.x;
    if (e < NE) {
        atomicAdd(&g_cnt[ei[e]], 1);        // out-degree (src)
        atomicAdd(&g_deg[ei[NE + e]], 1);   // in-degree (dst)
    }
}
__global__ void scan_kernel() {
    __shared__ int sh[1024];
    __shared__ int carry;
    if (threadIdx.x == 0) { carry = 0; g_rowptr[0] = 0; }
    __syncthreads();
    for (int base = 0; base < NN; base += 1024) {
        int i = base + threadIdx.x;
        int v = (i < NN) ? g_cnt[i] : 0;
        sh[threadIdx.x] = v;
        __syncthreads();
        for (int o = 1; o < 1024; o <<= 1) {
            int t = (threadIdx.x >= o) ? sh[threadIdx.x - o] : 0;
            __syncthreads();
            sh[threadIdx.x] += t;
            __syncthreads();
        }
        int base_off = carry;
        __syncthreads();
        if (i < NN) { g_rowptr[i + 1] = base_off + sh[threadIdx.x]; g_cnt[i] = 0; }
        __syncthreads();
        if (threadIdx.x == 0) carry = base_off + sh[1023];
        __syncthreads();
    }
}
__global__ void fill_kernel(const int* __restrict__ ei) {
    int e = blockIdx.x * blockDim.x + threadIdx.x;
    if (e >= NE) return;
    int s = ei[e];
    int pos = atomicAdd(&g_cnt[s], 1);
    g_adj[g_rowptr[s] + pos] = ei[NE + e];
}

// ---------------- fused convert + U (+BN apply, +agg zero) ------------------
// warp per node. lane covers channels {2l, 2l+1, 64+2l, 65+2l}.
__global__ __launch_bounds__(256) void convu_kernel(
    const float* __restrict__ X, const float* __restrict__ Wu,
    int bnidx, const float* __restrict__ gam, const float* __restrict__ bet)
{
    // zero g_agg for the upcoming scatter (640000 float4 == grid*block exactly)
    int idx = blockIdx.x * blockDim.x + threadIdx.x;
    ((float4*)g_agg)[idx] = make_float4(0.f, 0.f, 0.f, 0.f);

    __shared__ float wu[H * D];
    for (int i = threadIdx.x; i < H * D; i += blockDim.x) wu[i] = Wu[i];
    __syncthreads();

    const int n = blockIdx.x * 8 + (threadIdx.x >> 5);
    const int lane = threadIdx.x & 31;

    const float2* xr = (const float2*)(X + (size_t)n * D);
    float2 va = xr[lane];        // channels 2l, 2l+1
    float2 vb = xr[lane + 32];   // channels 64+2l, 65+2l

    if (bnidx >= 0) {
        const float invN = 1.f / (float)NN;
        float2 s01 = ((const float2*)g_sum[bnidx])[lane];
        float2 s23 = ((const float2*)g_sum[bnidx])[lane + 32];
        float2 q01 = ((const float2*)g_sumsq[bnidx])[lane];
        float2 q23 = ((const float2*)g_sumsq[bnidx])[lane + 32];
        float2 g01 = ((const float2*)gam)[lane];
        float2 g23 = ((const float2*)gam)[lane + 32];
        float2 b01 = ((const float2*)bet)[lane];
        float2 b23 = ((const float2*)bet)[lane + 32];
        float m, v;
        m = s01.x * invN; v = q01.x * invN - m * m;
        va.x = (va.x - m) * rsqrtf(v + BN_EPS) * g01.x + b01.x;
        m = s01.y * invN; v = q01.y * invN - m * m;
        va.y = (va.y - m) * rsqrtf(v + BN_EPS) * g01.y + b01.y;
        m = s23.x * invN; v = q23.x * invN - m * m;
        vb.x = (vb.x - m) * rsqrtf(v + BN_EPS) * g23.x + b23.x;
        m = s23.y * invN; v = q23.y * invN - m * m;
        vb.y = (vb.y - m) * rsqrtf(v + BN_EPS) * g23.y + b23.y;
    }

    // write Abig hi/lo (coalesced u32 stores)
    {
        u32* A32 = (u32*)g_Abig + (size_t)n * 128;
        __nv_bfloat162 h;
        h.x = __float2bfloat16(va.x); h.y = __float2bfloat16(va.y);
        A32[lane] = *(u32*)&h;
        float lx = va.x - __bfloat162float(h.x), ly = va.y - __bfloat162float(h.y);
        __nv_bfloat162 l; l.x = __float2bfloat16(lx); l.y = __float2bfloat16(ly);
        A32[lane + 64] = *(u32*)&l;
        h.x = __float2bfloat16(vb.x); h.y = __float2bfloat16(vb.y);
        A32[lane + 32] = *(u32*)&h;
        lx = vb.x - __bfloat162float(h.x); ly = vb.y - __bfloat162float(h.y);
        l.x = __float2bfloat16(lx); l.y = __float2bfloat16(ly);
        A32[lane + 96] = *(u32*)&l;
    }

    // U[h]
#pragma unroll
    for (int h = 0; h < H; h++) {
        const float2* w = (const float2*)(wu + h * D);
        float2 f0 = w[lane], f1 = w[lane + 32];
        float p = va.x * f0.x + va.y * f0.y + vb.x * f1.x + vb.y * f1.y;
#pragma unroll
        for (int o = 16; o; o >>= 1) p += __shfl_xor_sync(0xffffffffu, p, o);
        if (lane == 0) g_U[n * H + h] = p;
    }
}

// ---------------- B-resident mma GEMM (2 CTAs/SM, A-frag sharing) -----------
// grid (12, 24), 256 threads (8 warps, 2x4, warp tile 32x32).
// K-schedule (3-term split): hi0 x {B_hi0, B_lo0}; hi1 x {B_hi1, B_lo1};
//                            lo0 x B_hi0; lo1 x B_hi1.
__global__ void __launch_bounds__(256, 2) mma_y_kernel(int layer) {
    extern __shared__ char smem[];
    const u32 sb = smem_u32(smem);
    const int tid = threadIdx.x, wid = tid >> 5, lane = tid & 31;
    const int wm = (wid >> 2) * 32;
    const int wn = (wid & 3) * 32;
    const int bo = blockIdx.x * 128;
    const int g  = lane >> 2, tq = lane & 3;

    const u32 sB = sb;
    const u32 sA = sb + 4 * BCH;
    const __nv_bfloat16* Bbase = g_Bbig + (size_t)layer * HO * KTA;

    const int a_row = wm + (lane & 15);
    const int a_kb  = (lane >> 4) * 16;
    const int b_t   = lane >> 3;
    const int b_row = wn + ((b_t >> 1) * 8) + (lane & 7);
    const int b_kb  = (b_t & 1) * 16;

    {   // load B resident: 4 chunks x 128 rows x 128 B
        const int r = tid >> 1, hb = (tid & 1) * 64;
        const char* gB = (const char*)Bbase + (size_t)(bo + r) * (KTA * 2) + hb;
#pragma unroll
        for (int c = 0; c < 4; c++) {
            u32 dst = sB + c * BCH + r * ROWB + hb;
            const char* src = gB + c * 128;
#pragma unroll
            for (int j = 0; j < 4; j++) cp16(dst + j * 16, src + j * 16);
        }
    }

    const int ar = tid >> 2;
    const int aq = (tid & 3) * 32;
    auto loadA = [&](int buf, int bm, int coff) {
        const char* src = (const char*)g_Abig + (size_t)(bm + ar) * (KTA * 2) + coff + aq;
        u32 dst = sA + buf * ACH + ar * ROWB + aq;
        cp16(dst, src);
        cp16(dst + 16, src + 16);
    };

    const int bm0 = blockIdx.y * 64;
    loadA(0, bm0, 0);
    loadA(1, bm0, 128);
    asm volatile("cp.async.commit_group;");

    float acc[2][4][4];

    auto mma8 = [&](u32 (&a)[2][4], u32 (&b)[2][4]) {
#pragma unroll
        for (int i = 0; i < 2; i++)
#pragma unroll
            for (int j = 0; j < 4; j++) {
                const u32 b0 = b[j >> 1][(j & 1) * 2];
                const u32 b1 = b[j >> 1][(j & 1) * 2 + 1];
                asm volatile(
                    "mma.sync.aligned.m16n8k16.row.col.f32.bf16.bf16.f32 "
                    "{%0,%1,%2,%3}, {%4,%5,%6,%7}, {%8,%9}, {%0,%1,%2,%3};"
                    : "+f"(acc[i][j][0]), "+f"(acc[i][j][1]),
                      "+f"(acc[i][j][2]), "+f"(acc[i][j][3])
                    : "r"(a[i][0]), "r"(a[i][1]), "r"(a[i][2]), "r"(a[i][3]),
                      "r"(b0), "r"(b1));
            }
    };

    // A-fragment shared across two B chunks
    auto stepK2 = [&](u32 Ab, u32 Bb1, u32 Bb2) {
#pragma unroll
        for (int k = 0; k < 4; k++) {
            const int kb = k * 32;
            u32 a[2][4], b[2][4];
#pragma unroll
            for (int i = 0; i < 2; i++)
                ldsm4(a[i][0], a[i][1], a[i][2], a[i][3],
                      Ab + (a_row + i * 16) * ROWB + kb + a_kb);
#pragma unroll
            for (int jj = 0; jj < 2; jj++)
                ldsm4(b[jj][0], b[jj][1], b[jj][2], b[jj][3],
                      Bb1 + (b_row + jj * 16) * ROWB + kb + b_kb);
            mma8(a, b);
#pragma unroll
            for (int jj = 0; jj < 2; jj++)
                ldsm4(b[jj][0], b[jj][1], b[jj][2], b[jj][3],
                      Bb2 + (b_row + jj * 16) * ROWB + kb + b_kb);
            mma8(a, b);
        }
    };
    auto stepK1 = [&](u32 Ab, u32 Bb1) {
#pragma unroll
        for (int k = 0; k < 4; k++) {
            const int kb = k * 32;
            u32 a[2][4], b[2][4];
#pragma unroll
            for (int i = 0; i < 2; i++)
                ldsm4(a[i][0], a[i][1], a[i][2], a[i][3],
                      Ab + (a_row + i * 16) * ROWB + kb + a_kb);
#pragma unroll
            for (int jj = 0; jj < 2; jj++)
                ldsm4(b[jj][0], b[jj][1], b[jj][2], b[jj][3],
                      Bb1 + (b_row + jj * 16) * ROWB + kb + b_kb);
            mma8(a, b);
        }
    };

    for (int tmi = blockIdx.y; tmi < MTILES; tmi += 24) {
        const int bm = tmi * 64;
#pragma unroll
        for (int i = 0; i < 2; i++)
#pragma unroll
            for (int j = 0; j < 4; j++)
#pragma unroll
                for (int q = 0; q < 4; q++) acc[i][j][q] = 0.f;

        __syncthreads();                          // lo buffers free of prev readers
        loadA(2, bm, 256);                        // stream lo(t)
        loadA(3, bm, 384);
        asm volatile("cp.async.commit_group;");
        asm volatile("cp.async.wait_group 1;");   // hi(t) (+B on first iter) ready
        __syncthreads();

        stepK2(sA + 0 * ACH, sB + 0 * BCH, sB + 2 * BCH);  // hi0 x B_hi0, B_lo0
        stepK2(sA + 1 * ACH, sB + 1 * BCH, sB + 3 * BCH);  // hi1 x B_hi1, B_lo1

        __syncthreads();                          // hi reads complete
        const int nt = tmi + 24;
        if (nt < MTILES) {
            loadA(0, nt * 64, 0);                 // prefetch hi(t+1)
            loadA(1, nt * 64, 128);
            asm volatile("cp.async.commit_group;");
            asm volatile("cp.async.wait_group 1;"); // lo(t) ready
        } else {
            asm volatile("cp.async.wait_group 0;");
        }
        __syncthreads();

        stepK1(sA + 2 * ACH, sB + 0 * BCH);       // lo0 x B_hi0
        stepK1(sA + 3 * ACH, sB + 1 * BCH);       // lo1 x B_hi1

        // epilogue
#pragma unroll
        for (int i = 0; i < 2; i++) {
            int r0 = bm + wm + i * 16 + g;
            int r1 = r0 + 8;
#pragma unroll
            for (int j = 0; j < 4; j++) {
                int col = bo + wn + j * 8 + tq * 2;
                if (r0 < NN)
                    *(float2*)(g_Y + (size_t)r0 * HO + col) =
                        make_float2(acc[i][j][0], acc[i][j][1]);
                if (r1 < NN)
                    *(float2*)(g_Y + (size_t)r1 * HO + col) =
                        make_float2(acc[i][j][2], acc[i][j][3]);
            }
        }
    }
}

// ---------------- scatter: warp per SRC node, max-subtracted softmax --------
__global__ __launch_bounds__(256) void scatter_kernel(const float* __restrict__ cvec) {
    int warp = blockIdx.x * 8 + (threadIdx.x >> 5);
    int lane = threadIdx.x & 31;
    if (warp >= NN) return;
    const int s = warp;

    F4U yv[H];
    const float4* y4 = reinterpret_cast<const float4*>(g_Y + (size_t)s * HO) + lane;
#pragma unroll
    for (int h = 0; h < H; h++) yv[h].f = y4[h * 32];

    float us = 0.f, cl = 0.f;
    if (lane < H) { us = g_U[s * H + lane]; cl = __ldg(&cvec[lane]); }

    int row = g_rowptr[s], end = g_rowptr[s + 1];
    for (int i = row - 1; i < end; i++) {     // i == row-1 encodes the self loop
        int d = s;
        float ud = us;
        if (i >= row) {
            d = g_adj[i];
            ud = (lane < H) ? __ldg(&g_U[d * H + lane]) : 0.f;
        }
        float logit = (lane < H) ? (ud - us + cl) : -1e30f;
        float m = logit;
#pragma unroll
        for (int o = 16; o; o >>= 1) m = fmaxf(m, __shfl_xor_sync(0xffffffffu, m, o));
        float e = (lane < H) ? __expf(logit - m) : 0.f;
        float ss = e;
#pragma unroll
        for (int o = 16; o; o >>= 1) ss += __shfl_xor_sync(0xffffffffu, ss, o);
        float a = e / ss;

        u64 m0 = 0ull, m1 = 0ull;
#pragma unroll
        for (int h = 0; h < H; h++) {
            float ah = __shfl_sync(0xffffffffu, a, h);
            u64 a2 = pack2(ah, ah);
            m0 = ffma2(a2, yv[h].u[0], m0);
            m1 = ffma2(a2, yv[h].u[1], m1);
        }
        float r0, r1, r2, r3;
        unpack2(m0, r0, r1);
        unpack2(m1, r2, r3);
        red_add_v4(g_agg + (size_t)d * D + lane * 4, r0, r1, r2, r3);
    }
}

// ---------------- finalize: out = agg/deg + b (+relu, + BN stats) -----------
__global__ __launch_bounds__(256) void finalize_kernel(const float* __restrict__ bvec,
                                                       float* __restrict__ out,
                                                       int relu, int bnidx) {
    int c = threadIdx.x & 127;
    float bb = __ldg(&bvec[c]);
    float lsum = 0.f, lsq = 0.f;
    for (int i = blockIdx.x * blockDim.x + threadIdx.x; i < NN * D;
         i += gridDim.x * blockDim.x) {
        float v = g_agg[i] / (float)g_deg[i >> 7] + bb;
        if (relu) v = fmaxf(v, 0.f);
        out[i] = v;
        lsum += v; lsq += v * v;
    }
    if (bnidx >= 0) {
        __shared__ float s1[256], s2[256];
        s1[threadIdx.x] = lsum; s2[threadIdx.x] = lsq;
        __syncthreads();
        if (threadIdx.x < 128) {
            atomicAdd(&g_sum[bnidx][threadIdx.x],
                      s1[threadIdx.x] + s1[threadIdx.x + 128]);
            atomicAdd(&g_sumsq[bnidx][threadIdx.x],
                      s2[threadIdx.x] + s2[threadIdx.x + 128]);
        }
    }
}

// ---------------- weight convert (all 3 layers) ------------------------------
__global__ void convertw3_kernel(const float* __restrict__ W0,
                                 const float* __restrict__ W1,
                                 const float* __restrict__ W2) {
    int i = blockIdx.x * blockDim.x + threadIdx.x;
    if (i >= 3 * HO * D) return;
    int l = i / (HO * D);
    int j = i - l * (HO * D);
    const float* W = (l == 0) ? W0 : (l == 1) ? W1 : W2;
    float v = W[j];
    int o = j >> 7, c = j & 127;
    __nv_bfloat16 hi = __float2bfloat16(v);
    __nv_bfloat16 lo = __float2bfloat16(v - __bfloat162float(hi));
    size_t base = (size_t)l * HO * KTA + (size_t)o * KTA + c;
    g_Bbig[base]       = hi;
    g_Bbig[base + 128] = lo;
}

// ---------------- launch ----------------------------------------------------
static void launch_mma(int layer) {
    cudaFuncSetAttribute(mma_y_kernel, cudaFuncAttributeMaxDynamicSharedMemorySize, SMEM_MMA);
    mma_y_kernel<<<dim3(12, 24), 256, SMEM_MMA>>>(layer);
}

extern "C" void kernel_launch(void* const* d_in, const int* in_sizes, int n_in,
                              void* d_out, int out_size)
{
    const float* x  = (const float*)d_in[0];
    const int*   ei = (const int*)d_in[1];

    const float *Wlin[3], *Wu[3], *cv[3], *bv[3], *bng[2], *bnb[2];
    if (in_sizes[6] == H * D * D) {
        for (int l = 0; l < 3; l++) {
            Wlin[l] = (const float*)d_in[2 + 4 * l];
            Wu[l]   = (const float*)d_in[3 + 4 * l];
            cv[l]   = (const float*)d_in[4 + 4 * l];
            bv[l]   = (const float*)d_in[5 + 4 * l];
        }
        bng[0] = (const float*)d_in[14]; bnb[0] = (const float*)d_in[15];
        bng[1] = (const float*)d_in[16]; bnb[1] = (const float*)d_in[17];
    } else {
        Wlin[0] = (const float*)d_in[2];  Wu[0] = (const float*)d_in[3];
        cv[0]   = (const float*)d_in[4];  bv[0] = (const float*)d_in[5];
        bng[0]  = (const float*)d_in[6];  bnb[0] = (const float*)d_in[7];
        Wlin[1] = (const float*)d_in[8];  Wu[1] = (const float*)d_in[9];
        cv[1]   = (const float*)d_in[10]; bv[1] = (const float*)d_in[11];
        bng[1]  = (const float*)d_in[12]; bnb[1] = (const float*)d_in[13];
        Wlin[2] = (const float*)d_in[14]; Wu[2] = (const float*)d_in[15];
        cv[2]   = (const float*)d_in[16]; bv[2] = (const float*)d_in[17];
    }

    float* out = (float*)d_out;
    float* t = nullptr;
    cudaGetSymbolAddress((void**)&t, g_t);

    // ---- layer 0 front (launch index 3 == mma_y for the ncu -s window) ----
    convertw3_kernel<<<(3 * HO * D + 255) / 256, 256>>>(Wlin[0], Wlin[1], Wlin[2]); // 0
    init_kernel<<<(NN + 255) / 256, 256>>>();                                       // 1
    convu_kernel<<<2500, 256>>>(x, Wu[0], -1, nullptr, nullptr);                    // 2
    launch_mma(0);                                                                  // 3 <- profiled
    count_kernel<<<(NE + 255) / 256, 256>>>(ei);
    scan_kernel<<<1, 1024>>>();
    fill_kernel<<<(NE + 255) / 256, 256>>>(ei);
    scatter_kernel<<<(NN + 7) / 8, 256>>>(cv[0]);
    finalize_kernel<<<192, 256>>>(bv[0], t, 1, 0);

    // ---- layer 1 ----
    convu_kernel<<<2500, 256>>>(t, Wu[1], 0, bng[0], bnb[0]);
    launch_mma(1);
    scatter_kernel<<<(NN + 7) / 8, 256>>>(cv[1]);
    finalize_kernel<<<192, 256>>>(bv[1], t, 1, 1);

    // ---- layer 2 -> d_out ----
    convu_kernel<<<2500, 256>>>(t, Wu[2], 1, bng[1], bnb[1]);
    launch_mma(2);
    scatter_kernel<<<(NN + 7) / 8, 256>>>(cv[2]);
    finalize_kernel<<<192, 256>>>(bv[2], out, 0, -1);
}

// round 15
// speedup vs baseline: 1.3143x; 1.1105x over previous
#include <cuda_runtime.h>
#include <cuda_bf16.h>
#include <math.h>
#include <cstdint>

#define NN 20000
#define NE 320000
#define D  128
#define H  12
#define HO 1536          // H * D
#define BN_EPS 1e-5f
#define MPAD 20096       // 314 * 64
#define KTA 256          // [hi|lo] storage, logical K=384 via chunk reuse
#define MTILES 314       // MPAD / 64

// mma smem: rows of 64 bf16 data + 16B pad = 144 B -> LDSM conflict-free
#define ROWB   144
#define BCH    (128 * ROWB)          // 18432 B  (B chunk: 128 rows)
#define ACH    (64 * ROWB)           // 9216 B   (A chunk: 64 rows)
#define SMEM_MMA (4 * BCH + 4 * ACH) // 110592 B -> 2 CTAs/SM

typedef unsigned long long u64;
typedef uint32_t u32;

// ---------------- packed f32x2 helpers --------------------------------------
__device__ __forceinline__ u64 pack2(float lo, float hi) {
    u64 r; asm("mov.b64 %0, {%1,%2};" : "=l"(r) : "f"(lo), "f"(hi)); return r;
}
__device__ __forceinline__ u64 ffma2(u64 a, u64 b, u64 c) {
    u64 d; asm("fma.rn.f32x2 %0, %1, %2, %3;" : "=l"(d) : "l"(a), "l"(b), "l"(c)); return d;
}
__device__ __forceinline__ void unpack2(u64 v, float& lo, float& hi) {
    asm("mov.b64 {%0,%1}, %2;" : "=f"(lo), "=f"(hi) : "l"(v));
}
__device__ __forceinline__ void red_add_v4(float* p, float a, float b, float c, float d) {
    asm volatile("red.global.add.v4.f32 [%0], {%1,%2,%3,%4};"
                 :: "l"(p), "f"(a), "f"(b), "f"(c), "f"(d) : "memory");
}
union F4U { float4 f; u64 u[2]; };

// ---------------- mma building blocks ---------------------------------------
__device__ __forceinline__ u32 smem_u32(const void* p) {
    u32 a;
    asm("{ .reg .u64 t; cvta.to.shared.u64 t, %1; cvt.u32.u64 %0, t; }" : "=r"(a) : "l"(p));
    return a;
}
__device__ __forceinline__ void cp16(u32 saddr, const void* g) {
    asm volatile("cp.async.cg.shared.global [%0], [%1], 16;" :: "r"(saddr), "l"(g));
}
__device__ __forceinline__ void ldsm4(u32& r0, u32& r1, u32& r2, u32& r3, u32 addr) {
    asm volatile("ldmatrix.sync.aligned.m8n8.x4.shared.b16 {%0,%1,%2,%3}, [%4];"
                 : "=r"(r0), "=r"(r1), "=r"(r2), "=r"(r3) : "r"(addr));
}

// ---------------- scratch (device globals) ----------------------------------
__device__ __nv_bfloat16 g_Abig[(size_t)MPAD * KTA];      // [row, 256] = [hi|lo]
__device__ __nv_bfloat16 g_Bbig[(size_t)3 * HO * KTA];    // 3 layers of weights
__device__ float g_Y[(size_t)NN * HO];
__device__ float g_U[NN * H];
__device__ float g_t[NN * D];
__device__ float g_agg[NN * D];
__device__ int   g_deg[NN];           // in-degree incl self
__device__ float g_sum[2][D];
__device__ float g_sumsq[2][D];
__device__ int   g_rowptr[NN + 1];    // src-CSR
__device__ int   g_cnt[NN];
__device__ int   g_adj[NE];

// ---------------- prologue ---------------------------------------------------
__global__ void init_kernel() {
    int i = blockIdx.x * blockDim.x + threadIdx.x;
    if (i < NN) { g_deg[i] = 1; g_cnt[i] = 0; }
    if (i < D) {
        g_sum[0][i] = 0.f; g_sum[1][i] = 0.f;
        g_sumsq[0][i] = 0.f; g_sumsq[1][i] = 0.f;
    }
    // zero the padded tail rows of g_Abig (rows NN..MPAD-1)
    if (i < (MPAD - NN) * 128) {
        ((u32*)g_Abig)[(size_t)NN * 128 + i] = 0;
    }
}
__global__ void count_kernel(const int* __restrict__ ei) {
    int e = blockIdx.x * blockDim.x + threadIdx.x;
    if (e < NE) {
        atomicAdd(&g_cnt[ei[e]], 1);        // out-degree (src)
        atomicAdd(&g_deg[ei[NE + e]], 1);   // in-degree (dst)
    }
}
__global__ void scan_kernel() {
    __shared__ int sh[1024];
    __shared__ int carry;
    if (threadIdx.x == 0) { carry = 0; g_rowptr[0] = 0; }
    __syncthreads();
    for (int base = 0; base < NN; base += 1024) {
        int i = base + threadIdx.x;
        int v = (i < NN) ? g_cnt[i] : 0;
        sh[threadIdx.x] = v;
        __syncthreads();
        for (int o = 1; o < 1024; o <<= 1) {
            int t = (threadIdx.x >= o) ? sh[threadIdx.x - o] : 0;
            __syncthreads();
            sh[threadIdx.x] += t;
            __syncthreads();
        }
        int base_off = carry;
        __syncthreads();
        if (i < NN) { g_rowptr[i + 1] = base_off + sh[threadIdx.x]; g_cnt[i] = 0; }
        __syncthreads();
        if (threadIdx.x == 0) carry = base_off + sh[1023];
        __syncthreads();
    }
}
__global__ void fill_kernel(const int* __restrict__ ei) {
    int e = blockIdx.x * blockDim.x + threadIdx.x;
    if (e >= NE) return;
    int s = ei[e];
    int pos = atomicAdd(&g_cnt[s], 1);
    g_adj[g_rowptr[s] + pos] = ei[NE + e];
}

// ---------------- fused convert + U (+BN apply, +agg zero) ------------------
// warp per node. lane covers channels {2l, 2l+1, 64+2l, 65+2l}.
__global__ __launch_bounds__(256) void convu_kernel(
    const float* __restrict__ X, const float* __restrict__ Wu,
    int bnidx, const float* __restrict__ gam, const float* __restrict__ bet)
{
    // zero g_agg for the upcoming scatter (640000 float4 == grid*block exactly)
    int idx = blockIdx.x * blockDim.x + threadIdx.x;
    ((float4*)g_agg)[idx] = make_float4(0.f, 0.f, 0.f, 0.f);

    __shared__ float wu[H * D];
    for (int i = threadIdx.x; i < H * D; i += blockDim.x) wu[i] = Wu[i];
    __syncthreads();

    const int n = blockIdx.x * 8 + (threadIdx.x >> 5);
    const int lane = threadIdx.x & 31;

    const float2* xr = (const float2*)(X + (size_t)n * D);
    float2 va = xr[lane];        // channels 2l, 2l+1
    float2 vb = xr[lane + 32];   // channels 64+2l, 65+2l

    if (bnidx >= 0) {
        const float invN = 1.f / (float)NN;
        float2 s01 = ((const float2*)g_sum[bnidx])[lane];
        float2 s23 = ((const float2*)g_sum[bnidx])[lane + 32];
        float2 q01 = ((const float2*)g_sumsq[bnidx])[lane];
        float2 q23 = ((const float2*)g_sumsq[bnidx])[lane + 32];
        float2 g01 = ((const float2*)gam)[lane];
        float2 g23 = ((const float2*)gam)[lane + 32];
        float2 b01 = ((const float2*)bet)[lane];
        float2 b23 = ((const float2*)bet)[lane + 32];
        float m, v;
        m = s01.x * invN; v = q01.x * invN - m * m;
        va.x = (va.x - m) * rsqrtf(v + BN_EPS) * g01.x + b01.x;
        m = s01.y * invN; v = q01.y * invN - m * m;
        va.y = (va.y - m) * rsqrtf(v + BN_EPS) * g01.y + b01.y;
        m = s23.x * invN; v = q23.x * invN - m * m;
        vb.x = (vb.x - m) * rsqrtf(v + BN_EPS) * g23.x + b23.x;
        m = s23.y * invN; v = q23.y * invN - m * m;
        vb.y = (vb.y - m) * rsqrtf(v + BN_EPS) * g23.y + b23.y;
    }

    // write Abig hi/lo (coalesced u32 stores)
    {
        u32* A32 = (u32*)g_Abig + (size_t)n * 128;
        __nv_bfloat162 h;
        h.x = __float2bfloat16(va.x); h.y = __float2bfloat16(va.y);
        A32[lane] = *(u32*)&h;
        float lx = va.x - __bfloat162float(h.x), ly = va.y - __bfloat162float(h.y);
        __nv_bfloat162 l; l.x = __float2bfloat16(lx); l.y = __float2bfloat16(ly);
        A32[lane + 64] = *(u32*)&l;
        h.x = __float2bfloat16(vb.x); h.y = __float2bfloat16(vb.y);
        A32[lane + 32] = *(u32*)&h;
        lx = vb.x - __bfloat162float(h.x); ly = vb.y - __bfloat162float(h.y);
        l.x = __float2bfloat16(lx); l.y = __float2bfloat16(ly);
        A32[lane + 96] = *(u32*)&l;
    }

    // U[h]
#pragma unroll
    for (int h = 0; h < H; h++) {
        const float2* w = (const float2*)(wu + h * D);
        float2 f0 = w[lane], f1 = w[lane + 32];
        float p = va.x * f0.x + va.y * f0.y + vb.x * f1.x + vb.y * f1.y;
#pragma unroll
        for (int o = 16; o; o >>= 1) p += __shfl_xor_sync(0xffffffffu, p, o);
        if (lane == 0) g_U[n * H + h] = p;
    }
}

// ---------------- B-resident mma GEMM (2 CTAs/SM, A-frag sharing) -----------
__global__ void __launch_bounds__(256, 2) mma_y_kernel(int layer) {
    extern __shared__ char smem[];
    const u32 sb = smem_u32(smem);
    const int tid = threadIdx.x, wid = tid >> 5, lane = tid & 31;
    const int wm = (wid >> 2) * 32;
    const int wn = (wid & 3) * 32;
    const int bo = blockIdx.x * 128;
    const int g  = lane >> 2, tq = lane & 3;

    const u32 sB = sb;
    const u32 sA = sb + 4 * BCH;
    const __nv_bfloat16* Bbase = g_Bbig + (size_t)layer * HO * KTA;

    const int a_row = wm + (lane & 15);
    const int a_kb  = (lane >> 4) * 16;
    const int b_t   = lane >> 3;
    const int b_row = wn + ((b_t >> 1) * 8) + (lane & 7);
    const int b_kb  = (b_t & 1) * 16;

    {   // load B resident: 4 chunks x 128 rows x 128 B
        const int r = tid >> 1, hb = (tid & 1) * 64;
        const char* gB = (const char*)Bbase + (size_t)(bo + r) * (KTA * 2) + hb;
#pragma unroll
        for (int c = 0; c < 4; c++) {
            u32 dst = sB + c * BCH + r * ROWB + hb;
            const char* src = gB + c * 128;
#pragma unroll
            for (int j = 0; j < 4; j++) cp16(dst + j * 16, src + j * 16);
        }
    }

    const int ar = tid >> 2;
    const int aq = (tid & 3) * 32;
    auto loadA = [&](int buf, int bm, int coff) {
        const char* src = (const char*)g_Abig + (size_t)(bm + ar) * (KTA * 2) + coff + aq;
        u32 dst = sA + buf * ACH + ar * ROWB + aq;
        cp16(dst, src);
        cp16(dst + 16, src + 16);
    };

    const int bm0 = blockIdx.y * 64;
    loadA(0, bm0, 0);
    loadA(1, bm0, 128);
    asm volatile("cp.async.commit_group;");

    float acc[2][4][4];

    auto mma8 = [&](u32 (&a)[2][4], u32 (&b)[2][4]) {
#pragma unroll
        for (int i = 0; i < 2; i++)
#pragma unroll
            for (int j = 0; j < 4; j++) {
                const u32 b0 = b[j >> 1][(j & 1) * 2];
                const u32 b1 = b[j >> 1][(j & 1) * 2 + 1];
                asm volatile(
                    "mma.sync.aligned.m16n8k16.row.col.f32.bf16.bf16.f32 "
                    "{%0,%1,%2,%3}, {%4,%5,%6,%7}, {%8,%9}, {%0,%1,%2,%3};"
                    : "+f"(acc[i][j][0]), "+f"(acc[i][j][1]),
                      "+f"(acc[i][j][2]), "+f"(acc[i][j][3])
                    : "r"(a[i][0]), "r"(a[i][1]), "r"(a[i][2]), "r"(a[i][3]),
                      "r"(b0), "r"(b1));
            }
    };

    auto stepK2 = [&](u32 Ab, u32 Bb1, u32 Bb2) {
#pragma unroll
        for (int k = 0; k < 4; k++) {
            const int kb = k * 32;
            u32 a[2][4], b[2][4];
#pragma unroll
            for (int i = 0; i < 2; i++)
                ldsm4(a[i][0], a[i][1], a[i][2], a[i][3],
                      Ab + (a_row + i * 16) * ROWB + kb + a_kb);
#pragma unroll
            for (int jj = 0; jj < 2; jj++)
                ldsm4(b[jj][0], b[jj][1], b[jj][2], b[jj][3],
                      Bb1 + (b_row + jj * 16) * ROWB + kb + b_kb);
            mma8(a, b);
#pragma unroll
            for (int jj = 0; jj < 2; jj++)
                ldsm4(b[jj][0], b[jj][1], b[jj][2], b[jj][3],
                      Bb2 + (b_row + jj * 16) * ROWB + kb + b_kb);
            mma8(a, b);
        }
    };
    auto stepK1 = [&](u32 Ab, u32 Bb1) {
#pragma unroll
        for (int k = 0; k < 4; k++) {
            const int kb = k * 32;
            u32 a[2][4], b[2][4];
#pragma unroll
            for (int i = 0; i < 2; i++)
                ldsm4(a[i][0], a[i][1], a[i][2], a[i][3],
                      Ab + (a_row + i * 16) * ROWB + kb + a_kb);
#pragma unroll
            for (int jj = 0; jj < 2; jj++)
                ldsm4(b[jj][0], b[jj][1], b[jj][2], b[jj][3],
                      Bb1 + (b_row + jj * 16) * ROWB + kb + b_kb);
            mma8(a, b);
        }
    };

    for (int tmi = blockIdx.y; tmi < MTILES; tmi += 24) {
        const int bm = tmi * 64;
#pragma unroll
        for (int i = 0; i < 2; i++)
#pragma unroll
            for (int j = 0; j < 4; j++)
#pragma unroll
                for (int q = 0; q < 4; q++) acc[i][j][q] = 0.f;

        __syncthreads();
        loadA(2, bm, 256);
        loadA(3, bm, 384);
        asm volatile("cp.async.commit_group;");
        asm volatile("cp.async.wait_group 1;");
        __syncthreads();

        stepK2(sA + 0 * ACH, sB + 0 * BCH, sB + 2 * BCH);  // hi0 x B_hi0, B_lo0
        stepK2(sA + 1 * ACH, sB + 1 * BCH, sB + 3 * BCH);  // hi1 x B_hi1, B_lo1

        __syncthreads();
        const int nt = tmi + 24;
        if (nt < MTILES) {
            loadA(0, nt * 64, 0);
            loadA(1, nt * 64, 128);
            asm volatile("cp.async.commit_group;");
            asm volatile("cp.async.wait_group 1;");
        } else {
            asm volatile("cp.async.wait_group 0;");
        }
        __syncthreads();

        stepK1(sA + 2 * ACH, sB + 0 * BCH);       // lo0 x B_hi0
        stepK1(sA + 3 * ACH, sB + 1 * BCH);       // lo1 x B_hi1

#pragma unroll
        for (int i = 0; i < 2; i++) {
            int r0 = bm + wm + i * 16 + g;
            int r1 = r0 + 8;
#pragma unroll
            for (int j = 0; j < 4; j++) {
                int col = bo + wn + j * 8 + tq * 2;
                if (r0 < NN)
                    *(float2*)(g_Y + (size_t)r0 * HO + col) =
                        make_float2(acc[i][j][0], acc[i][j][1]);
                if (r1 < NN)
                    *(float2*)(g_Y + (size_t)r1 * HO + col) =
                        make_float2(acc[i][j][2], acc[i][j][3]);
            }
        }
    }
}

// ---------------- scatter: warp per SRC node, pipelined U loads -------------
// Max-subtracted softmax (REQUIRED: logits can exceed expf range in layers>=1).
__global__ __launch_bounds__(256) void scatter_kernel(const float* __restrict__ cvec) {
    int warp = blockIdx.x * 8 + (threadIdx.x >> 5);
    int lane = threadIdx.x & 31;
    if (warp >= NN) return;
    const int s = warp;

    F4U yv[H];
    const float4* y4 = reinterpret_cast<const float4*>(g_Y + (size_t)s * HO) + lane;
#pragma unroll
    for (int h = 0; h < H; h++) yv[h].f = y4[h * 32];

    float us = 0.f, cl = 0.f;
    if (lane < H) { us = g_U[s * H + lane]; cl = __ldg(&cvec[lane]); }

    const int row = g_rowptr[s], end = g_rowptr[s + 1];

    // software pipeline: prefetch next edge's dst + U_d
    int d_cur = s;
    float ud_cur = us;                      // self loop first (i = row-1)
    for (int i = row - 1; i < end; i++) {
        const int d = d_cur;
        const float ud = ud_cur;
        if (i + 1 < end) {                   // prefetch next edge
            d_cur = g_adj[i + 1];
            ud_cur = (lane < H) ? __ldg(&g_U[d_cur * H + lane]) : 0.f;
        }

        float logit = (lane < H) ? (ud - us + cl) : -1e30f;
        float m = logit;
#pragma unroll
        for (int o = 16; o; o >>= 1) m = fmaxf(m, __shfl_xor_sync(0xffffffffu, m, o));
        float e = (lane < H) ? __expf(logit - m) : 0.f;
        float ss = e;
#pragma unroll
        for (int o = 16; o; o >>= 1) ss += __shfl_xor_sync(0xffffffffu, ss, o);
        float a = e / ss;

        u64 m0 = 0ull, m1 = 0ull;
#pragma unroll
        for (int h = 0; h < H; h++) {
            float ah = __shfl_sync(0xffffffffu, a, h);
            u64 a2 = pack2(ah, ah);
            m0 = ffma2(a2, yv[h].u[0], m0);
            m1 = ffma2(a2, yv[h].u[1], m1);
        }
        float r0, r1, r2, r3;
        unpack2(m0, r0, r1);
        unpack2(m1, r2, r3);
        red_add_v4(g_agg + (size_t)d * D + lane * 4, r0, r1, r2, r3);
    }
}

// ---------------- finalize: out = agg/deg + b (+relu, + BN stats) -----------
__global__ __launch_bounds__(256) void finalize_kernel(const float* __restrict__ bvec,
                                                       float* __restrict__ out,
                                                       int relu, int bnidx) {
    int c = threadIdx.x & 127;
    float bb = __ldg(&bvec[c]);
    float lsum = 0.f, lsq = 0.f;
    for (int i = blockIdx.x * blockDim.x + threadIdx.x; i < NN * D;
         i += gridDim.x * blockDim.x) {
        float v = g_agg[i] / (float)g_deg[i >> 7] + bb;
        if (relu) v = fmaxf(v, 0.f);
        out[i] = v;
        lsum += v; lsq += v * v;
    }
    if (bnidx >= 0) {
        __shared__ float s1[256], s2[256];
        s1[threadIdx.x] = lsum; s2[threadIdx.x] = lsq;
        __syncthreads();
        if (threadIdx.x < 128) {
            atomicAdd(&g_sum[bnidx][threadIdx.x],
                      s1[threadIdx.x] + s1[threadIdx.x + 128]);
            atomicAdd(&g_sumsq[bnidx][threadIdx.x],
                      s2[threadIdx.x] + s2[threadIdx.x + 128]);
        }
    }
}

// ---------------- weight convert (all 3 layers) ------------------------------
__global__ void convertw3_kernel(const float* __restrict__ W0,
                                 const float* __restrict__ W1,
                                 const float* __restrict__ W2) {
    int i = blockIdx.x * blockDim.x + threadIdx.x;
    if (i >= 3 * HO * D) return;
    int l = i / (HO * D);
    int j = i - l * (HO * D);
    const float* W = (l == 0) ? W0 : (l == 1) ? W1 : W2;
    float v = W[j];
    int o = j >> 7, c = j & 127;
    __nv_bfloat16 hi = __float2bfloat16(v);
    __nv_bfloat16 lo = __float2bfloat16(v - __bfloat162float(hi));
    size_t base = (size_t)l * HO * KTA + (size_t)o * KTA + c;
    g_Bbig[base]       = hi;
    g_Bbig[base + 128] = lo;
}

// ---------------- launch ----------------------------------------------------
static void launch_mma(int layer) {
    cudaFuncSetAttribute(mma_y_kernel, cudaFuncAttributeMaxDynamicSharedMemorySize, SMEM_MMA);
    mma_y_kernel<<<dim3(12, 24), 256, SMEM_MMA>>>(layer);
}

extern "C" void kernel_launch(void* const* d_in, const int* in_sizes, int n_in,
                              void* d_out, int out_size)
{
    const float* x  = (const float*)d_in[0];
    const int*   ei = (const int*)d_in[1];

    const float *Wlin[3], *Wu[3], *cv[3], *bv[3], *bng[2], *bnb[2];
    if (in_sizes[6] == H * D * D) {
        for (int l = 0; l < 3; l++) {
            Wlin[l] = (const float*)d_in[2 + 4 * l];
            Wu[l]   = (const float*)d_in[3 + 4 * l];
            cv[l]   = (const float*)d_in[4 + 4 * l];
            bv[l]   = (const float*)d_in[5 + 4 * l];
        }
        bng[0] = (const float*)d_in[14]; bnb[0] = (const float*)d_in[15];
        bng[1] = (const float*)d_in[16]; bnb[1] = (const float*)d_in[17];
    } else {
        Wlin[0] = (const float*)d_in[2];  Wu[0] = (const float*)d_in[3];
        cv[0]   = (const float*)d_in[4];  bv[0] = (const float*)d_in[5];
        bng[0]  = (const float*)d_in[6];  bnb[0] = (const float*)d_in[7];
        Wlin[1] = (const float*)d_in[8];  Wu[1] = (const float*)d_in[9];
        cv[1]   = (const float*)d_in[10]; bv[1] = (const float*)d_in[11];
        bng[1]  = (const float*)d_in[12]; bnb[1] = (const float*)d_in[13];
        Wlin[2] = (const float*)d_in[14]; Wu[2] = (const float*)d_in[15];
        cv[2]   = (const float*)d_in[16]; bv[2] = (const float*)d_in[17];
    }

    float* out = (float*)d_out;
    float* t = nullptr;
    cudaGetSymbolAddress((void**)&t, g_t);

    // ---- layer 0 front (launch index 3 == mma_y for the ncu -s window) ----
    convertw3_kernel<<<(3 * HO * D + 255) / 256, 256>>>(Wlin[0], Wlin[1], Wlin[2]); // 0
    init_kernel<<<(NN + 255) / 256, 256>>>();                                       // 1
    convu_kernel<<<2500, 256>>>(x, Wu[0], -1, nullptr, nullptr);                    // 2
    launch_mma(0);                                                                  // 3 <- profiled
    count_kernel<<<(NE + 255) / 256, 256>>>(ei);
    scan_kernel<<<1, 1024>>>();
    fill_kernel<<<(NE + 255) / 256, 256>>>(ei);
    scatter_kernel<<<(NN + 7) / 8, 256>>>(cv[0]);
    finalize_kernel<<<192, 256>>>(bv[0], t, 1, 0);

    // ---- layer 1 ----
    convu_kernel<<<2500, 256>>>(t, Wu[1], 0, bng[0], bnb[0]);
    launch_mma(1);
    scatter_kernel<<<(NN + 7) / 8, 256>>>(cv[1]);
    finalize_kernel<<<192, 256>>>(bv[1], t, 1, 1);

    // ---- layer 2 -> d_out ----
    convu_kernel<<<2500, 256>>>(t, Wu[2], 1, bng[1], bnb[1]);
    launch_mma(2);
    scatter_kernel<<<(NN + 7) / 8, 256>>>(cv[2]);
    finalize_kernel<<<192, 256>>>(bv[2], out, 0, -1);
}

// round 16
// speedup vs baseline: 1.3328x; 1.0141x over previous
#include <cuda_runtime.h>
#include <cuda_bf16.h>
#include <math.h>
#include <cstdint>

#define NN 20000
#define NE 320000
#define D  128
#define H  12
#define HO 1536          // H * D
#define BN_EPS 1e-5f
#define MPAD 20096       // 314 * 64
#define KTA 256          // [hi|lo] storage, logical K=384 via chunk reuse
#define MTILES 314       // MPAD / 64

// mma smem: rows of 64 bf16 data + 16B pad = 144 B -> LDSM conflict-free
#define ROWB   144
#define BCH    (128 * ROWB)          // 18432 B  (B chunk: 128 rows)
#define ACH    (64 * ROWB)           // 9216 B   (A chunk: 64 rows)
#define SMEM_MMA (4 * BCH + 4 * ACH) // 110592 B -> 2 CTAs/SM

typedef unsigned long long u64;
typedef uint32_t u32;

// ---------------- packed f32x2 helpers --------------------------------------
__device__ __forceinline__ u64 pack2(float lo, float hi) {
    u64 r; asm("mov.b64 %0, {%1,%2};" : "=l"(r) : "f"(lo), "f"(hi)); return r;
}
__device__ __forceinline__ u64 ffma2(u64 a, u64 b, u64 c) {
    u64 d; asm("fma.rn.f32x2 %0, %1, %2, %3;" : "=l"(d) : "l"(a), "l"(b), "l"(c)); return d;
}
__device__ __forceinline__ void unpack2(u64 v, float& lo, float& hi) {
    asm("mov.b64 {%0,%1}, %2;" : "=f"(lo), "=f"(hi) : "l"(v));
}
__device__ __forceinline__ void red_add_v4(float* p, float a, float b, float c, float d) {
    asm volatile("red.global.add.v4.f32 [%0], {%1,%2,%3,%4};"
                 :: "l"(p), "f"(a), "f"(b), "f"(c), "f"(d) : "memory");
}
union F4U { float4 f; u64 u[2]; };

// ---------------- mma building blocks ---------------------------------------
__device__ __forceinline__ u32 smem_u32(const void* p) {
    u32 a;
    asm("{ .reg .u64 t; cvta.to.shared.u64 t, %1; cvt.u32.u64 %0, t; }" : "=r"(a) : "l"(p));
    return a;
}
__device__ __forceinline__ void cp16(u32 saddr, const void* g) {
    asm volatile("cp.async.cg.shared.global [%0], [%1], 16;" :: "r"(saddr), "l"(g));
}
__device__ __forceinline__ void ldsm4(u32& r0, u32& r1, u32& r2, u32& r3, u32 addr) {
    asm volatile("ldmatrix.sync.aligned.m8n8.x4.shared.b16 {%0,%1,%2,%3}, [%4];"
                 : "=r"(r0), "=r"(r1), "=r"(r2), "=r"(r3) : "r"(addr));
}

// ---------------- scratch (device globals) ----------------------------------
__device__ __nv_bfloat16 g_Abig[(size_t)MPAD * KTA];      // [row, 256] = [hi|lo]
__device__ __nv_bfloat16 g_Bbig[(size_t)3 * HO * KTA];    // 3 layers of weights
__device__ float g_Y[(size_t)NN * HO];
__device__ float g_U[NN * H];
__device__ float g_t[NN * D];
__device__ float g_agg[NN * D];
__device__ int   g_deg[NN];           // in-degree incl self
__device__ float g_sum[2][D];
__device__ float g_sumsq[2][D];
__device__ int   g_rowptr[NN + 1];    // src-CSR
__device__ int   g_cnt[NN];
__device__ int   g_adj[NE];

// ---------------- prologue ---------------------------------------------------
__global__ void init_kernel() {
    int i = blockIdx.x * blockDim.x + threadIdx.x;
    if (i < NN) { g_deg[i] = 1; g_cnt[i] = 0; }
    if (i < D) {
        g_sum[0][i] = 0.f; g_sum[1][i] = 0.f;
        g_sumsq[0][i] = 0.f; g_sumsq[1][i] = 0.f;
    }
    // zero the padded tail rows of g_Abig (rows NN..MPAD-1)
    if (i < (MPAD - NN) * 128) {
        ((u32*)g_Abig)[(size_t)NN * 128 + i] = 0;
    }
}
__global__ void count_kernel(const int* __restrict__ ei) {
    int e = blockIdx.x * blockDim.x + threadIdx.x;
    if (e < NE) {
        atomicAdd(&g_cnt[ei[e]], 1);        // out-degree (src)
        atomicAdd(&g_deg[ei[NE + e]], 1);   // in-degree (dst)
    }
}
__global__ void scan_kernel() {
    __shared__ int sh[1024];
    __shared__ int carry;
    if (threadIdx.x == 0) { carry = 0; g_rowptr[0] = 0; }
    __syncthreads();
    for (int base = 0; base < NN; base += 1024) {
        int i = base + threadIdx.x;
        int v = (i < NN) ? g_cnt[i] : 0;
        sh[threadIdx.x] = v;
        __syncthreads();
        for (int o = 1; o < 1024; o <<= 1) {
            int t = (threadIdx.x >= o) ? sh[threadIdx.x - o] : 0;
            __syncthreads();
            sh[threadIdx.x] += t;
            __syncthreads();
        }
        int base_off = carry;
        __syncthreads();
        if (i < NN) { g_rowptr[i + 1] = base_off + sh[threadIdx.x]; g_cnt[i] = 0; }
        __syncthreads();
        if (threadIdx.x == 0) carry = base_off + sh[1023];
        __syncthreads();
    }
}
__global__ void fill_kernel(const int* __restrict__ ei) {
    int e = blockIdx.x * blockDim.x + threadIdx.x;
    if (e >= NE) return;
    int s = ei[e];
    int pos = atomicAdd(&g_cnt[s], 1);
    g_adj[g_rowptr[s] + pos] = ei[NE + e];
}

// ---------------- fused convert + U (+BN apply, +agg zero) ------------------
// warp per node. lane covers channels {2l, 2l+1, 64+2l, 65+2l}.
__global__ __launch_bounds__(256) void convu_kernel(
    const float* __restrict__ X, const float* __restrict__ Wu,
    int bnidx, const float* __restrict__ gam, const float* __restrict__ bet)
{
    // zero g_agg for the upcoming scatter (640000 float4 == grid*block exactly)
    int idx = blockIdx.x * blockDim.x + threadIdx.x;
    ((float4*)g_agg)[idx] = make_float4(0.f, 0.f, 0.f, 0.f);

    __shared__ float wu[H * D];
    for (int i = threadIdx.x; i < H * D; i += blockDim.x) wu[i] = Wu[i];
    __syncthreads();

    const int n = blockIdx.x * 8 + (threadIdx.x >> 5);
    const int lane = threadIdx.x & 31;

    const float2* xr = (const float2*)(X + (size_t)n * D);
    float2 va = xr[lane];        // channels 2l, 2l+1
    float2 vb = xr[lane + 32];   // channels 64+2l, 65+2l

    if (bnidx >= 0) {
        const float invN = 1.f / (float)NN;
        float2 s01 = ((const float2*)g_sum[bnidx])[lane];
        float2 s23 = ((const float2*)g_sum[bnidx])[lane + 32];
        float2 q01 = ((const float2*)g_sumsq[bnidx])[lane];
        float2 q23 = ((const float2*)g_sumsq[bnidx])[lane + 32];
        float2 g01 = ((const float2*)gam)[lane];
        float2 g23 = ((const float2*)gam)[lane + 32];
        float2 b01 = ((const float2*)bet)[lane];
        float2 b23 = ((const float2*)bet)[lane + 32];
        float m, v;
        m = s01.x * invN; v = q01.x * invN - m * m;
        va.x = (va.x - m) * rsqrtf(v + BN_EPS) * g01.x + b01.x;
        m = s01.y * invN; v = q01.y * invN - m * m;
        va.y = (va.y - m) * rsqrtf(v + BN_EPS) * g01.y + b01.y;
        m = s23.x * invN; v = q23.x * invN - m * m;
        vb.x = (vb.x - m) * rsqrtf(v + BN_EPS) * g23.x + b23.x;
        m = s23.y * invN; v = q23.y * invN - m * m;
        vb.y = (vb.y - m) * rsqrtf(v + BN_EPS) * g23.y + b23.y;
    }

    // write Abig hi/lo (coalesced u32 stores)
    {
        u32* A32 = (u32*)g_Abig + (size_t)n * 128;
        __nv_bfloat162 h;
        h.x = __float2bfloat16(va.x); h.y = __float2bfloat16(va.y);
        A32[lane] = *(u32*)&h;
        float lx = va.x - __bfloat162float(h.x), ly = va.y - __bfloat162float(h.y);
        __nv_bfloat162 l; l.x = __float2bfloat16(lx); l.y = __float2bfloat16(ly);
        A32[lane + 64] = *(u32*)&l;
        h.x = __float2bfloat16(vb.x); h.y = __float2bfloat16(vb.y);
        A32[lane + 32] = *(u32*)&h;
        lx = vb.x - __bfloat162float(h.x); ly = vb.y - __bfloat162float(h.y);
        l.x = __float2bfloat16(lx); l.y = __float2bfloat16(ly);
        A32[lane + 96] = *(u32*)&l;
    }

    // U[h]
#pragma unroll
    for (int h = 0; h < H; h++) {
        const float2* w = (const float2*)(wu + h * D);
        float2 f0 = w[lane], f1 = w[lane + 32];
        float p = va.x * f0.x + va.y * f0.y + vb.x * f1.x + vb.y * f1.y;
#pragma unroll
        for (int o = 16; o; o >>= 1) p += __shfl_xor_sync(0xffffffffu, p, o);
        if (lane == 0) g_U[n * H + h] = p;
    }
}

// ---------------- B-resident mma GEMM (2 CTAs/SM, A-frag sharing) -----------
__global__ void __launch_bounds__(256, 2) mma_y_kernel(int layer) {
    extern __shared__ char smem[];
    const u32 sb = smem_u32(smem);
    const int tid = threadIdx.x, wid = tid >> 5, lane = tid & 31;
    const int wm = (wid >> 2) * 32;
    const int wn = (wid & 3) * 32;
    const int bo = blockIdx.x * 128;
    const int g  = lane >> 2, tq = lane & 3;

    const u32 sB = sb;
    const u32 sA = sb + 4 * BCH;
    const __nv_bfloat16* Bbase = g_Bbig + (size_t)layer * HO * KTA;

    const int a_row = wm + (lane & 15);
    const int a_kb  = (lane >> 4) * 16;
    const int b_t   = lane >> 3;
    const int b_row = wn + ((b_t >> 1) * 8) + (lane & 7);
    const int b_kb  = (b_t & 1) * 16;

    {   // load B resident: 4 chunks x 128 rows x 128 B
        const int r = tid >> 1, hb = (tid & 1) * 64;
        const char* gB = (const char*)Bbase + (size_t)(bo + r) * (KTA * 2) + hb;
#pragma unroll
        for (int c = 0; c < 4; c++) {
            u32 dst = sB + c * BCH + r * ROWB + hb;
            const char* src = gB + c * 128;
#pragma unroll
            for (int j = 0; j < 4; j++) cp16(dst + j * 16, src + j * 16);
        }
    }

    const int ar = tid >> 2;
    const int aq = (tid & 3) * 32;
    auto loadA = [&](int buf, int bm, int coff) {
        const char* src = (const char*)g_Abig + (size_t)(bm + ar) * (KTA * 2) + coff + aq;
        u32 dst = sA + buf * ACH + ar * ROWB + aq;
        cp16(dst, src);
        cp16(dst + 16, src + 16);
    };

    const int bm0 = blockIdx.y * 64;
    loadA(0, bm0, 0);
    loadA(1, bm0, 128);
    asm volatile("cp.async.commit_group;");

    float acc[2][4][4];

    auto mma8 = [&](u32 (&a)[2][4], u32 (&b)[2][4]) {
#pragma unroll
        for (int i = 0; i < 2; i++)
#pragma unroll
            for (int j = 0; j < 4; j++) {
                const u32 b0 = b[j >> 1][(j & 1) * 2];
                const u32 b1 = b[j >> 1][(j & 1) * 2 + 1];
                asm volatile(
                    "mma.sync.aligned.m16n8k16.row.col.f32.bf16.bf16.f32 "
                    "{%0,%1,%2,%3}, {%4,%5,%6,%7}, {%8,%9}, {%0,%1,%2,%3};"
                    : "+f"(acc[i][j][0]), "+f"(acc[i][j][1]),
                      "+f"(acc[i][j][2]), "+f"(acc[i][j][3])
                    : "r"(a[i][0]), "r"(a[i][1]), "r"(a[i][2]), "r"(a[i][3]),
                      "r"(b0), "r"(b1));
            }
    };

    auto stepK2 = [&](u32 Ab, u32 Bb1, u32 Bb2) {
#pragma unroll
        for (int k = 0; k < 4; k++) {
            const int kb = k * 32;
            u32 a[2][4], b[2][4];
#pragma unroll
            for (int i = 0; i < 2; i++)
                ldsm4(a[i][0], a[i][1], a[i][2], a[i][3],
                      Ab + (a_row + i * 16) * ROWB + kb + a_kb);
#pragma unroll
            for (int jj = 0; jj < 2; jj++)
                ldsm4(b[jj][0], b[jj][1], b[jj][2], b[jj][3],
                      Bb1 + (b_row + jj * 16) * ROWB + kb + b_kb);
            mma8(a, b);
#pragma unroll
            for (int jj = 0; jj < 2; jj++)
                ldsm4(b[jj][0], b[jj][1], b[jj][2], b[jj][3],
                      Bb2 + (b_row + jj * 16) * ROWB + kb + b_kb);
            mma8(a, b);
        }
    };
    auto stepK1 = [&](u32 Ab, u32 Bb1) {
#pragma unroll
        for (int k = 0; k < 4; k++) {
            const int kb = k * 32;
            u32 a[2][4], b[2][4];
#pragma unroll
            for (int i = 0; i < 2; i++)
                ldsm4(a[i][0], a[i][1], a[i][2], a[i][3],
                      Ab + (a_row + i * 16) * ROWB + kb + a_kb);
#pragma unroll
            for (int jj = 0; jj < 2; jj++)
                ldsm4(b[jj][0], b[jj][1], b[jj][2], b[jj][3],
                      Bb1 + (b_row + jj * 16) * ROWB + kb + b_kb);
            mma8(a, b);
        }
    };

    for (int tmi = blockIdx.y; tmi < MTILES; tmi += 24) {
        const int bm = tmi * 64;
#pragma unroll
        for (int i = 0; i < 2; i++)
#pragma unroll
            for (int j = 0; j < 4; j++)
#pragma unroll
                for (int q = 0; q < 4; q++) acc[i][j][q] = 0.f;

        __syncthreads();
        loadA(2, bm, 256);
        loadA(3, bm, 384);
        asm volatile("cp.async.commit_group;");
        asm volatile("cp.async.wait_group 1;");
        __syncthreads();

        stepK2(sA + 0 * ACH, sB + 0 * BCH, sB + 2 * BCH);  // hi0 x B_hi0, B_lo0
        stepK2(sA + 1 * ACH, sB + 1 * BCH, sB + 3 * BCH);  // hi1 x B_hi1, B_lo1

        __syncthreads();
        const int nt = tmi + 24;
        if (nt < MTILES) {
            loadA(0, nt * 64, 0);
            loadA(1, nt * 64, 128);
            asm volatile("cp.async.commit_group;");
            asm volatile("cp.async.wait_group 1;");
        } else {
            asm volatile("cp.async.wait_group 0;");
        }
        __syncthreads();

        stepK1(sA + 2 * ACH, sB + 0 * BCH);       // lo0 x B_hi0
        stepK1(sA + 3 * ACH, sB + 1 * BCH);       // lo1 x B_hi1

#pragma unroll
        for (int i = 0; i < 2; i++) {
            int r0 = bm + wm + i * 16 + g;
            int r1 = r0 + 8;
#pragma unroll
            for (int j = 0; j < 4; j++) {
                int col = bo + wn + j * 8 + tq * 2;
                if (r0 < NN)
                    *(float2*)(g_Y + (size_t)r0 * HO + col) =
                        make_float2(acc[i][j][0], acc[i][j][1]);
                if (r1 < NN)
                    *(float2*)(g_Y + (size_t)r1 * HO + col) =
                        make_float2(acc[i][j][2], acc[i][j][3]);
            }
        }
    }
}

// ---------------- scatter: warp/SRC, 2-edge unroll, 16-lane softmax ---------
// Max-subtracted softmax (REQUIRED for layers >= 1). Reductions use 4-step
// 16-lane butterflies: lanes 12..15 carry identities (-1e30 / 0), broadcasts
// read lanes 0..11 only. a on lanes >= 16 is garbage and never read.
__global__ __launch_bounds__(256) void scatter_kernel(const float* __restrict__ cvec) {
    int warp = blockIdx.x * 8 + (threadIdx.x >> 5);
    int lane = threadIdx.x & 31;
    if (warp >= NN) return;
    const int s = warp;

    F4U yv[H];
    const float4* y4 = reinterpret_cast<const float4*>(g_Y + (size_t)s * HO) + lane;
#pragma unroll
    for (int h = 0; h < H; h++) yv[h].f = y4[h * 32];

    float us = 0.f, base = -1e30f;
    if (lane < H) {
        us = g_U[s * H + lane];
        base = __ldg(&cvec[lane]) - us;     // logit = U_d + base
    }
    float* aggp = g_agg + (size_t)0;

    // attention for one edge given U_d (valid on lanes < H)
    auto attn = [&](float ud) -> float {
        float logit = (lane < H) ? (ud + base) : -1e30f;
        float m = logit;
#pragma unroll
        for (int o = 8; o; o >>= 1) m = fmaxf(m, __shfl_xor_sync(0xffffffffu, m, o));
        float e = (lane < H) ? __expf(logit - m) : 0.f;
        float ss = e;
#pragma unroll
        for (int o = 8; o; o >>= 1) ss += __shfl_xor_sync(0xffffffffu, ss, o);
        return e * __frcp_rn(ss);
    };
    auto emit = [&](int d, float a) {
        u64 m0 = 0ull, m1 = 0ull;
#pragma unroll
        for (int h = 0; h < H; h++) {
            float ah = __shfl_sync(0xffffffffu, a, h);
            u64 a2 = pack2(ah, ah);
            m0 = ffma2(a2, yv[h].u[0], m0);
            m1 = ffma2(a2, yv[h].u[1], m1);
        }
        float r0, r1, r2, r3;
        unpack2(m0, r0, r1);
        unpack2(m1, r2, r3);
        red_add_v4(aggp + (size_t)d * D + lane * 4, r0, r1, r2, r3);
    };

    const int row = g_rowptr[s], end = g_rowptr[s + 1];

    // prefetch first pair while the self-loop computes
    int dA = s, dB = s;
    float uA = us, uB = us;
    if (row < end) {
        dA = g_adj[row];
        uA = (lane < H) ? __ldg(&g_U[dA * H + lane]) : 0.f;
    }
    if (row + 1 < end) {
        dB = g_adj[row + 1];
        uB = (lane < H) ? __ldg(&g_U[dB * H + lane]) : 0.f;
    }

    emit(s, attn(us));                       // self loop

    for (int i = row; i < end; i += 2) {
        const int d0 = dA, d1 = dB;
        const float u0 = uA, u1 = uB;
        const bool has1 = (i + 1 < end);
        const int ni = i + 2;
        if (ni < end) {                      // prefetch next pair
            dA = g_adj[ni];
            uA = (lane < H) ? __ldg(&g_U[dA * H + lane]) : 0.f;
            if (ni + 1 < end) {
                dB = g_adj[ni + 1];
                uB = (lane < H) ? __ldg(&g_U[dB * H + lane]) : 0.f;
            }
        }
        // two independent softmax chains (interleave in the scheduler)
        float l0 = (lane < H) ? (u0 + base) : -1e30f;
        float l1 = (lane < H) ? (u1 + base) : -1e30f;
        float m0 = l0, m1 = l1;
#pragma unroll
        for (int o = 8; o; o >>= 1) {
            m0 = fmaxf(m0, __shfl_xor_sync(0xffffffffu, m0, o));
            m1 = fmaxf(m1, __shfl_xor_sync(0xffffffffu, m1, o));
        }
        float e0 = (lane < H) ? __expf(l0 - m0) : 0.f;
        float e1 = (lane < H) ? __expf(l1 - m1) : 0.f;
        float s0 = e0, s1 = e1;
#pragma unroll
        for (int o = 8; o; o >>= 1) {
            s0 += __shfl_xor_sync(0xffffffffu, s0, o);
            s1 += __shfl_xor_sync(0xffffffffu, s1, o);
        }
        float a0 = e0 * __frcp_rn(s0);
        float a1 = e1 * __frcp_rn(s1);

        emit(d0, a0);
        if (has1) emit(d1, a1);
    }
}

// ---------------- finalize: out = agg/deg + b (+relu, + BN stats) -----------
__global__ __launch_bounds__(256) void finalize_kernel(const float* __restrict__ bvec,
                                                       float* __restrict__ out,
                                                       int relu, int bnidx) {
    int c = threadIdx.x & 127;
    float bb = __ldg(&bvec[c]);
    float lsum = 0.f, lsq = 0.f;
    for (int i = blockIdx.x * blockDim.x + threadIdx.x; i < NN * D;
         i += gridDim.x * blockDim.x) {
        float v = g_agg[i] / (float)g_deg[i >> 7] + bb;
        if (relu) v = fmaxf(v, 0.f);
        out[i] = v;
        lsum += v; lsq += v * v;
    }
    if (bnidx >= 0) {
        __shared__ float s1[256], s2[256];
        s1[threadIdx.x] = lsum; s2[threadIdx.x] = lsq;
        __syncthreads();
        if (threadIdx.x < 128) {
            atomicAdd(&g_sum[bnidx][threadIdx.x],
                      s1[threadIdx.x] + s1[threadIdx.x + 128]);
            atomicAdd(&g_sumsq[bnidx][threadIdx.x],
                      s2[threadIdx.x] + s2[threadIdx.x + 128]);
        }
    }
}

// ---------------- weight convert (all 3 layers) ------------------------------
__global__ void convertw3_kernel(const float* __restrict__ W0,
                                 const float* __restrict__ W1,
                                 const float* __restrict__ W2) {
    int i = blockIdx.x * blockDim.x + threadIdx.x;
    if (i >= 3 * HO * D) return;
    int l = i / (HO * D);
    int j = i - l * (HO * D);
    const float* W = (l == 0) ? W0 : (l == 1) ? W1 : W2;
    float v = W[j];
    int o = j >> 7, c = j & 127;
    __nv_bfloat16 hi = __float2bfloat16(v);
    __nv_bfloat16 lo = __float2bfloat16(v - __bfloat162float(hi));
    size_t base = (size_t)l * HO * KTA + (size_t)o * KTA + c;
    g_Bbig[base]       = hi;
    g_Bbig[base + 128] = lo;
}

// ---------------- launch ----------------------------------------------------
static void launch_mma(int layer) {
    cudaFuncSetAttribute(mma_y_kernel, cudaFuncAttributeMaxDynamicSharedMemorySize, SMEM_MMA);
    mma_y_kernel<<<dim3(12, 24), 256, SMEM_MMA>>>(layer);
}

extern "C" void kernel_launch(void* const* d_in, const int* in_sizes, int n_in,
                              void* d_out, int out_size)
{
    const float* x  = (const float*)d_in[0];
    const int*   ei = (const int*)d_in[1];

    const float *Wlin[3], *Wu[3], *cv[3], *bv[3], *bng[2], *bnb[2];
    if (in_sizes[6] == H * D * D) {
        for (int l = 0; l < 3; l++) {
            Wlin[l] = (const float*)d_in[2 + 4 * l];
            Wu[l]   = (const float*)d_in[3 + 4 * l];
            cv[l]   = (const float*)d_in[4 + 4 * l];
            bv[l]   = (const float*)d_in[5 + 4 * l];
        }
        bng[0] = (const float*)d_in[14]; bnb[0] = (const float*)d_in[15];
        bng[1] = (const float*)d_in[16]; bnb[1] = (const float*)d_in[17];
    } else {
        Wlin[0] = (const float*)d_in[2];  Wu[0] = (const float*)d_in[3];
        cv[0]   = (const float*)d_in[4];  bv[0] = (const float*)d_in[5];
        bng[0]  = (const float*)d_in[6];  bnb[0] = (const float*)d_in[7];
        Wlin[1] = (const float*)d_in[8];  Wu[1] = (const float*)d_in[9];
        cv[1]   = (const float*)d_in[10]; bv[1] = (const float*)d_in[11];
        bng[1]  = (const float*)d_in[12]; bnb[1] = (const float*)d_in[13];
        Wlin[2] = (const float*)d_in[14]; Wu[2] = (const float*)d_in[15];
        cv[2]   = (const float*)d_in[16]; bv[2] = (const float*)d_in[17];
    }

    float* out = (float*)d_out;
    float* t = nullptr;
    cudaGetSymbolAddress((void**)&t, g_t);

    // ---- layer 0 front (launch index 3 == mma_y for the ncu -s window) ----
    convertw3_kernel<<<(3 * HO * D + 255) / 256, 256>>>(Wlin[0], Wlin[1], Wlin[2]); // 0
    init_kernel<<<(NN + 255) / 256, 256>>>();                                       // 1
    convu_kernel<<<2500, 256>>>(x, Wu[0], -1, nullptr, nullptr);                    // 2
    launch_mma(0);                                                                  // 3 <- profiled
    count_kernel<<<(NE + 255) / 256, 256>>>(ei);
    scan_kernel<<<1, 1024>>>();
    fill_kernel<<<(NE + 255) / 256, 256>>>(ei);
    scatter_kernel<<<(NN + 7) / 8, 256>>>(cv[0]);
    finalize_kernel<<<192, 256>>>(bv[0], t, 1, 0);

    // ---- layer 1 ----
    convu_kernel<<<2500, 256>>>(t, Wu[1], 0, bng[0], bnb[0]);
    launch_mma(1);
    scatter_kernel<<<(NN + 7) / 8, 256>>>(cv[1]);
    finalize_kernel<<<192, 256>>>(bv[1], t, 1, 1);

    // ---- layer 2 -> d_out ----
    convu_kernel<<<2500, 256>>>(t, Wu[2], 1, bng[1], bnb[1]);
    launch_mma(2);
    scatter_kernel<<<(NN + 7) / 8, 256>>>(cv[2]);
    finalize_kernel<<<192, 256>>>(bv[2], out, 0, -1);
}

// round 17
// speedup vs baseline: 1.3486x; 1.0118x over previous
#include <cuda_runtime.h>
#include <cuda_bf16.h>
#include <math.h>
#include <cstdint>

#define NN 20000
#define NE 320000
#define D  128
#define H  12
#define HO 1536          // H * D
#define BN_EPS 1e-5f
#define MPAD 20096       // 314 * 64
#define KTA 256          // [hi|lo] storage, logical K=384 via chunk reuse
#define MTILES 314       // MPAD / 64

// mma smem: rows of 64 bf16 data + 16B pad = 144 B -> LDSM conflict-free
#define ROWB   144
#define BCH    (128 * ROWB)          // 18432 B  (B chunk: 128 rows)
#define ACH    (64 * ROWB)           // 9216 B   (A chunk: 64 rows)
#define SMEM_MMA (4 * BCH + 4 * ACH) // 110592 B -> 2 CTAs/SM

typedef unsigned long long u64;
typedef uint32_t u32;

// ---------------- packed f32x2 helpers --------------------------------------
__device__ __forceinline__ u64 pack2(float lo, float hi) {
    u64 r; asm("mov.b64 %0, {%1,%2};" : "=l"(r) : "f"(lo), "f"(hi)); return r;
}
__device__ __forceinline__ u64 ffma2(u64 a, u64 b, u64 c) {
    u64 d; asm("fma.rn.f32x2 %0, %1, %2, %3;" : "=l"(d) : "l"(a), "l"(b), "l"(c)); return d;
}
__device__ __forceinline__ void unpack2(u64 v, float& lo, float& hi) {
    asm("mov.b64 {%0,%1}, %2;" : "=f"(lo), "=f"(hi) : "l"(v));
}
__device__ __forceinline__ void red_add_v4(float* p, float a, float b, float c, float d) {
    asm volatile("red.global.add.v4.f32 [%0], {%1,%2,%3,%4};"
                 :: "l"(p), "f"(a), "f"(b), "f"(c), "f"(d) : "memory");
}
union F4U { float4 f; u64 u[2]; };

// ---------------- mma building blocks ---------------------------------------
__device__ __forceinline__ u32 smem_u32(const void* p) {
    u32 a;
    asm("{ .reg .u64 t; cvta.to.shared.u64 t, %1; cvt.u32.u64 %0, t; }" : "=r"(a) : "l"(p));
    return a;
}
__device__ __forceinline__ void cp16(u32 saddr, const void* g) {
    asm volatile("cp.async.cg.shared.global [%0], [%1], 16;" :: "r"(saddr), "l"(g));
}
__device__ __forceinline__ void ldsm4(u32& r0, u32& r1, u32& r2, u32& r3, u32 addr) {
    asm volatile("ldmatrix.sync.aligned.m8n8.x4.shared.b16 {%0,%1,%2,%3}, [%4];"
                 : "=r"(r0), "=r"(r1), "=r"(r2), "=r"(r3) : "r"(addr));
}

// ---------------- scratch (device globals) ----------------------------------
__device__ __nv_bfloat16 g_Abig[(size_t)MPAD * KTA];      // [row, 256] = [hi|lo]
__device__ __nv_bfloat16 g_Bbig[(size_t)3 * HO * KTA];    // 3 layers of weights
__device__ float g_Y[(size_t)NN * HO];
__device__ float g_U[NN * H];
__device__ float g_t[NN * D];
__device__ float g_agg[NN * D];
__device__ int   g_deg[NN];           // in-degree incl self
__device__ float g_sum[2][D];
__device__ float g_sumsq[2][D];
__device__ int   g_rowptr[NN + 1];    // src-CSR
__device__ int   g_cnt[NN];
__device__ int   g_adj[NE];

// ---------------- prologue ---------------------------------------------------
__global__ void init_kernel() {
    int i = blockIdx.x * blockDim.x + threadIdx.x;
    if (i < NN) { g_deg[i] = 1; g_cnt[i] = 0; }
    if (i < D) {
        g_sum[0][i] = 0.f; g_sum[1][i] = 0.f;
        g_sumsq[0][i] = 0.f; g_sumsq[1][i] = 0.f;
    }
    // zero the padded tail rows of g_Abig (rows NN..MPAD-1)
    if (i < (MPAD - NN) * 128) {
        ((u32*)g_Abig)[(size_t)NN * 128 + i] = 0;
    }
}
__global__ void count_kernel(const int* __restrict__ ei) {
    int e = blockIdx.x * blockDim.x + threadIdx.x;
    if (e < NE) {
        atomicAdd(&g_cnt[ei[e]], 1);        // out-degree (src)
        atomicAdd(&g_deg[ei[NE + e]], 1);   // in-degree (dst)
    }
}
__global__ void scan_kernel() {
    __shared__ int sh[1024];
    __shared__ int carry;
    if (threadIdx.x == 0) { carry = 0; g_rowptr[0] = 0; }
    __syncthreads();
    for (int base = 0; base < NN; base += 1024) {
        int i = base + threadIdx.x;
        int v = (i < NN) ? g_cnt[i] : 0;
        sh[threadIdx.x] = v;
        __syncthreads();
        for (int o = 1; o < 1024; o <<= 1) {
            int t = (threadIdx.x >= o) ? sh[threadIdx.x - o] : 0;
            __syncthreads();
            sh[threadIdx.x] += t;
            __syncthreads();
        }
        int base_off = carry;
        __syncthreads();
        if (i < NN) { g_rowptr[i + 1] = base_off + sh[threadIdx.x]; g_cnt[i] = 0; }
        __syncthreads();
        if (threadIdx.x == 0) carry = base_off + sh[1023];
        __syncthreads();
    }
}
__global__ void fill_kernel(const int* __restrict__ ei) {
    int e = blockIdx.x * blockDim.x + threadIdx.x;
    if (e >= NE) return;
    int s = ei[e];
    int pos = atomicAdd(&g_cnt[s], 1);
    g_adj[g_rowptr[s] + pos] = ei[NE + e];
}

// ---------------- fused convert + U (+BN apply, +agg zero) ------------------
// warp per node. lane covers channels {2l, 2l+1, 64+2l, 65+2l}.
__global__ __launch_bounds__(256) void convu_kernel(
    const float* __restrict__ X, const float* __restrict__ Wu,
    int bnidx, const float* __restrict__ gam, const float* __restrict__ bet)
{
    // zero g_agg for the upcoming scatter (640000 float4 == grid*block exactly)
    int idx = blockIdx.x * blockDim.x + threadIdx.x;
    ((float4*)g_agg)[idx] = make_float4(0.f, 0.f, 0.f, 0.f);

    __shared__ float wu[H * D];
    for (int i = threadIdx.x; i < H * D; i += blockDim.x) wu[i] = Wu[i];
    __syncthreads();

    const int n = blockIdx.x * 8 + (threadIdx.x >> 5);
    const int lane = threadIdx.x & 31;

    const float2* xr = (const float2*)(X + (size_t)n * D);
    float2 va = xr[lane];        // channels 2l, 2l+1
    float2 vb = xr[lane + 32];   // channels 64+2l, 65+2l

    if (bnidx >= 0) {
        const float invN = 1.f / (float)NN;
        float2 s01 = ((const float2*)g_sum[bnidx])[lane];
        float2 s23 = ((const float2*)g_sum[bnidx])[lane + 32];
        float2 q01 = ((const float2*)g_sumsq[bnidx])[lane];
        float2 q23 = ((const float2*)g_sumsq[bnidx])[lane + 32];
        float2 g01 = ((const float2*)gam)[lane];
        float2 g23 = ((const float2*)gam)[lane + 32];
        float2 b01 = ((const float2*)bet)[lane];
        float2 b23 = ((const float2*)bet)[lane + 32];
        float m, v;
        m = s01.x * invN; v = q01.x * invN - m * m;
        va.x = (va.x - m) * rsqrtf(v + BN_EPS) * g01.x + b01.x;
        m = s01.y * invN; v = q01.y * invN - m * m;
        va.y = (va.y - m) * rsqrtf(v + BN_EPS) * g01.y + b01.y;
        m = s23.x * invN; v = q23.x * invN - m * m;
        vb.x = (vb.x - m) * rsqrtf(v + BN_EPS) * g23.x + b23.x;
        m = s23.y * invN; v = q23.y * invN - m * m;
        vb.y = (vb.y - m) * rsqrtf(v + BN_EPS) * g23.y + b23.y;
    }

    // write Abig hi/lo (coalesced u32 stores)
    {
        u32* A32 = (u32*)g_Abig + (size_t)n * 128;
        __nv_bfloat162 h;
        h.x = __float2bfloat16(va.x); h.y = __float2bfloat16(va.y);
        A32[lane] = *(u32*)&h;
        float lx = va.x - __bfloat162float(h.x), ly = va.y - __bfloat162float(h.y);
        __nv_bfloat162 l; l.x = __float2bfloat16(lx); l.y = __float2bfloat16(ly);
        A32[lane + 64] = *(u32*)&l;
        h.x = __float2bfloat16(vb.x); h.y = __float2bfloat16(vb.y);
        A32[lane + 32] = *(u32*)&h;
        lx = vb.x - __bfloat162float(h.x); ly = vb.y - __bfloat162float(h.y);
        l.x = __float2bfloat16(lx); l.y = __float2bfloat16(ly);
        A32[lane + 96] = *(u32*)&l;
    }

    // U[h]
#pragma unroll
    for (int h = 0; h < H; h++) {
        const float2* w = (const float2*)(wu + h * D);
        float2 f0 = w[lane], f1 = w[lane + 32];
        float p = va.x * f0.x + va.y * f0.y + vb.x * f1.x + vb.y * f1.y;
#pragma unroll
        for (int o = 16; o; o >>= 1) p += __shfl_xor_sync(0xffffffffu, p, o);
        if (lane == 0) g_U[n * H + h] = p;
    }
}

// ---------------- B-resident mma GEMM (2 CTAs/SM, A-frag sharing) -----------
__global__ void __launch_bounds__(256, 2) mma_y_kernel(int layer) {
    extern __shared__ char smem[];
    const u32 sb = smem_u32(smem);
    const int tid = threadIdx.x, wid = tid >> 5, lane = tid & 31;
    const int wm = (wid >> 2) * 32;
    const int wn = (wid & 3) * 32;
    const int bo = blockIdx.x * 128;
    const int g  = lane >> 2, tq = lane & 3;

    const u32 sB = sb;
    const u32 sA = sb + 4 * BCH;
    const __nv_bfloat16* Bbase = g_Bbig + (size_t)layer * HO * KTA;

    const int a_row = wm + (lane & 15);
    const int a_kb  = (lane >> 4) * 16;
    const int b_t   = lane >> 3;
    const int b_row = wn + ((b_t >> 1) * 8) + (lane & 7);
    const int b_kb  = (b_t & 1) * 16;

    {   // load B resident: 4 chunks x 128 rows x 128 B
        const int r = tid >> 1, hb = (tid & 1) * 64;
        const char* gB = (const char*)Bbase + (size_t)(bo + r) * (KTA * 2) + hb;
#pragma unroll
        for (int c = 0; c < 4; c++) {
            u32 dst = sB + c * BCH + r * ROWB + hb;
            const char* src = gB + c * 128;
#pragma unroll
            for (int j = 0; j < 4; j++) cp16(dst + j * 16, src + j * 16);
        }
    }

    const int ar = tid >> 2;
    const int aq = (tid & 3) * 32;
    auto loadA = [&](int buf, int bm, int coff) {
        const char* src = (const char*)g_Abig + (size_t)(bm + ar) * (KTA * 2) + coff + aq;
        u32 dst = sA + buf * ACH + ar * ROWB + aq;
        cp16(dst, src);
        cp16(dst + 16, src + 16);
    };

    const int bm0 = blockIdx.y * 64;
    loadA(0, bm0, 0);
    loadA(1, bm0, 128);
    asm volatile("cp.async.commit_group;");

    float acc[2][4][4];

    auto mma8 = [&](u32 (&a)[2][4], u32 (&b)[2][4]) {
#pragma unroll
        for (int i = 0; i < 2; i++)
#pragma unroll
            for (int j = 0; j < 4; j++) {
                const u32 b0 = b[j >> 1][(j & 1) * 2];
                const u32 b1 = b[j >> 1][(j & 1) * 2 + 1];
                asm volatile(
                    "mma.sync.aligned.m16n8k16.row.col.f32.bf16.bf16.f32 "
                    "{%0,%1,%2,%3}, {%4,%5,%6,%7}, {%8,%9}, {%0,%1,%2,%3};"
                    : "+f"(acc[i][j][0]), "+f"(acc[i][j][1]),
                      "+f"(acc[i][j][2]), "+f"(acc[i][j][3])
                    : "r"(a[i][0]), "r"(a[i][1]), "r"(a[i][2]), "r"(a[i][3]),
                      "r"(b0), "r"(b1));
            }
    };

    auto stepK2 = [&](u32 Ab, u32 Bb1, u32 Bb2) {
#pragma unroll
        for (int k = 0; k < 4; k++) {
            const int kb = k * 32;
            u32 a[2][4], b[2][4];
#pragma unroll
            for (int i = 0; i < 2; i++)
                ldsm4(a[i][0], a[i][1], a[i][2], a[i][3],
                      Ab + (a_row + i * 16) * ROWB + kb + a_kb);
#pragma unroll
            for (int jj = 0; jj < 2; jj++)
                ldsm4(b[jj][0], b[jj][1], b[jj][2], b[jj][3],
                      Bb1 + (b_row + jj * 16) * ROWB + kb + b_kb);
            mma8(a, b);
#pragma unroll
            for (int jj = 0; jj < 2; jj++)
                ldsm4(b[jj][0], b[jj][1], b[jj][2], b[jj][3],
                      Bb2 + (b_row + jj * 16) * ROWB + kb + b_kb);
            mma8(a, b);
        }
    };
    auto stepK1 = [&](u32 Ab, u32 Bb1) {
#pragma unroll
        for (int k = 0; k < 4; k++) {
            const int kb = k * 32;
            u32 a[2][4], b[2][4];
#pragma unroll
            for (int i = 0; i < 2; i++)
                ldsm4(a[i][0], a[i][1], a[i][2], a[i][3],
                      Ab + (a_row + i * 16) * ROWB + kb + a_kb);
#pragma unroll
            for (int jj = 0; jj < 2; jj++)
                ldsm4(b[jj][0], b[jj][1], b[jj][2], b[jj][3],
                      Bb1 + (b_row + jj * 16) * ROWB + kb + b_kb);
            mma8(a, b);
        }
    };

    for (int tmi = blockIdx.y; tmi < MTILES; tmi += 24) {
        const int bm = tmi * 64;
#pragma unroll
        for (int i = 0; i < 2; i++)
#pragma unroll
            for (int j = 0; j < 4; j++)
#pragma unroll
                for (int q = 0; q < 4; q++) acc[i][j][q] = 0.f;

        __syncthreads();
        loadA(2, bm, 256);
        loadA(3, bm, 384);
        asm volatile("cp.async.commit_group;");
        asm volatile("cp.async.wait_group 1;");
        __syncthreads();

        stepK2(sA + 0 * ACH, sB + 0 * BCH, sB + 2 * BCH);  // hi0 x B_hi0, B_lo0
        stepK2(sA + 1 * ACH, sB + 1 * BCH, sB + 3 * BCH);  // hi1 x B_hi1, B_lo1

        __syncthreads();
        const int nt = tmi + 24;
        if (nt < MTILES) {
            loadA(0, nt * 64, 0);
            loadA(1, nt * 64, 128);
            asm volatile("cp.async.commit_group;");
            asm volatile("cp.async.wait_group 1;");
        } else {
            asm volatile("cp.async.wait_group 0;");
        }
        __syncthreads();

        stepK1(sA + 2 * ACH, sB + 0 * BCH);       // lo0 x B_hi0
        stepK1(sA + 3 * ACH, sB + 1 * BCH);       // lo1 x B_hi1

#pragma unroll
        for (int i = 0; i < 2; i++) {
            int r0 = bm + wm + i * 16 + g;
            int r1 = r0 + 8;
#pragma unroll
            for (int j = 0; j < 4; j++) {
                int col = bo + wn + j * 8 + tq * 2;
                if (r0 < NN)
                    *(float2*)(g_Y + (size_t)r0 * HO + col) =
                        make_float2(acc[i][j][0], acc[i][j][1]);
                if (r1 < NN)
                    *(float2*)(g_Y + (size_t)r1 * HO + col) =
                        make_float2(acc[i][j][2], acc[i][j][3]);
            }
        }
    }
}

// ---------------- scatter: 2 warps per SRC node (edge-list split) -----------
// Max-subtracted softmax (REQUIRED for layers >= 1). 16-lane butterflies:
// lanes 12..15 carry identities; broadcasts read lanes 0..11 only.
__global__ __launch_bounds__(256) void scatter_kernel(const float* __restrict__ cvec) {
    int warp = blockIdx.x * 8 + (threadIdx.x >> 5);
    int lane = threadIdx.x & 31;
    if (warp >= 2 * NN) return;
    const int s = warp >> 1;
    const int half = warp & 1;

    F4U yv[H];
    const float4* y4 = reinterpret_cast<const float4*>(g_Y + (size_t)s * HO) + lane;
#pragma unroll
    for (int h = 0; h < H; h++) yv[h].f = y4[h * 32];

    float us = 0.f, base = -1e30f;
    if (lane < H) {
        us = g_U[s * H + lane];
        base = __ldg(&cvec[lane]) - us;     // logit = U_d + base
    }

    auto attn = [&](float ud) -> float {
        float logit = (lane < H) ? (ud + base) : -1e30f;
        float m = logit;
#pragma unroll
        for (int o = 8; o; o >>= 1) m = fmaxf(m, __shfl_xor_sync(0xffffffffu, m, o));
        float e = (lane < H) ? __expf(logit - m) : 0.f;
        float ss = e;
#pragma unroll
        for (int o = 8; o; o >>= 1) ss += __shfl_xor_sync(0xffffffffu, ss, o);
        return e * __frcp_rn(ss);
    };
    auto emit = [&](int d, float a) {
        // two independent accumulator chains per half-vector
        u64 m0a = 0ull, m0b = 0ull, m1a = 0ull, m1b = 0ull;
#pragma unroll
        for (int h = 0; h < H; h += 2) {
            float ah0 = __shfl_sync(0xffffffffu, a, h);
            float ah1 = __shfl_sync(0xffffffffu, a, h + 1);
            u64 a20 = pack2(ah0, ah0);
            u64 a21 = pack2(ah1, ah1);
            m0a = ffma2(a20, yv[h].u[0], m0a);
            m1a = ffma2(a20, yv[h].u[1], m1a);
            m0b = ffma2(a21, yv[h + 1].u[0], m0b);
            m1b = ffma2(a21, yv[h + 1].u[1], m1b);
        }
        float r0, r1, r2, r3, t0, t1, t2, t3;
        unpack2(m0a, r0, r1); unpack2(m0b, t0, t1);
        unpack2(m1a, r2, r3); unpack2(m1b, t2, t3);
        red_add_v4(g_agg + (size_t)d * D + lane * 4,
                   r0 + t0, r1 + t1, r2 + t2, r3 + t3);
    };

    const int row = g_rowptr[s], end = g_rowptr[s + 1];
    const int mid = row + ((end - row) >> 1);
    const int lo = half ? mid : row;
    const int hi = half ? end : mid;

    // prefetch first pair
    int dA = s, dB = s;
    float uA = us, uB = us;
    if (lo < hi) {
        dA = g_adj[lo];
        uA = (lane < H) ? __ldg(&g_U[dA * H + lane]) : 0.f;
    }
    if (lo + 1 < hi) {
        dB = g_adj[lo + 1];
        uB = (lane < H) ? __ldg(&g_U[dB * H + lane]) : 0.f;
    }

    if (!half) emit(s, attn(us));            // self loop (half 0 only)

    for (int i = lo; i < hi; i += 2) {
        const int d0 = dA, d1 = dB;
        const float u0 = uA, u1 = uB;
        const bool has1 = (i + 1 < hi);
        const int ni = i + 2;
        if (ni < hi) {                        // prefetch next pair
            dA = g_adj[ni];
            uA = (lane < H) ? __ldg(&g_U[dA * H + lane]) : 0.f;
            if (ni + 1 < hi) {
                dB = g_adj[ni + 1];
                uB = (lane < H) ? __ldg(&g_U[dB * H + lane]) : 0.f;
            }
        }
        float l0 = (lane < H) ? (u0 + base) : -1e30f;
        float l1 = (lane < H) ? (u1 + base) : -1e30f;
        float m0 = l0, m1 = l1;
#pragma unroll
        for (int o = 8; o; o >>= 1) {
            m0 = fmaxf(m0, __shfl_xor_sync(0xffffffffu, m0, o));
            m1 = fmaxf(m1, __shfl_xor_sync(0xffffffffu, m1, o));
        }
        float e0 = (lane < H) ? __expf(l0 - m0) : 0.f;
        float e1 = (lane < H) ? __expf(l1 - m1) : 0.f;
        float s0 = e0, s1 = e1;
#pragma unroll
        for (int o = 8; o; o >>= 1) {
            s0 += __shfl_xor_sync(0xffffffffu, s0, o);
            s1 += __shfl_xor_sync(0xffffffffu, s1, o);
        }
        float a0 = e0 * __frcp_rn(s0);
        float a1 = e1 * __frcp_rn(s1);

        emit(d0, a0);
        if (has1) emit(d1, a1);
    }
}

// ---------------- finalize: out = agg/deg + b (+relu, + BN stats) -----------
__global__ __launch_bounds__(256) void finalize_kernel(const float* __restrict__ bvec,
                                                       float* __restrict__ out,
                                                       int relu, int bnidx) {
    int c = threadIdx.x & 127;
    float bb = __ldg(&bvec[c]);
    float lsum = 0.f, lsq = 0.f;
    for (int i = blockIdx.x * blockDim.x + threadIdx.x; i < NN * D;
         i += gridDim.x * blockDim.x) {
        float v = g_agg[i] / (float)g_deg[i >> 7] + bb;
        if (relu) v = fmaxf(v, 0.f);
        out[i] = v;
        lsum += v; lsq += v * v;
    }
    if (bnidx >= 0) {
        __shared__ float s1[256], s2[256];
        s1[threadIdx.x] = lsum; s2[threadIdx.x] = lsq;
        __syncthreads();
        if (threadIdx.x < 128) {
            atomicAdd(&g_sum[bnidx][threadIdx.x],
                      s1[threadIdx.x] + s1[threadIdx.x + 128]);
            atomicAdd(&g_sumsq[bnidx][threadIdx.x],
                      s2[threadIdx.x] + s2[threadIdx.x + 128]);
        }
    }
}

// ---------------- weight convert (all 3 layers) ------------------------------
__global__ void convertw3_kernel(const float* __restrict__ W0,
                                 const float* __restrict__ W1,
                                 const float* __restrict__ W2) {
    int i = blockIdx.x * blockDim.x + threadIdx.x;
    if (i >= 3 * HO * D) return;
    int l = i / (HO * D);
    int j = i - l * (HO * D);
    const float* W = (l == 0) ? W0 : (l == 1) ? W1 : W2;
    float v = W[j];
    int o = j >> 7, c = j & 127;
    __nv_bfloat16 hi = __float2bfloat16(v);
    __nv_bfloat16 lo = __float2bfloat16(v - __bfloat162float(hi));
    size_t base = (size_t)l * HO * KTA + (size_t)o * KTA + c;
    g_Bbig[base]       = hi;
    g_Bbig[base + 128] = lo;
}

// ---------------- launch ----------------------------------------------------
static void launch_mma(int layer) {
    cudaFuncSetAttribute(mma_y_kernel, cudaFuncAttributeMaxDynamicSharedMemorySize, SMEM_MMA);
    mma_y_kernel<<<dim3(12, 24), 256, SMEM_MMA>>>(layer);
}

extern "C" void kernel_launch(void* const* d_in, const int* in_sizes, int n_in,
                              void* d_out, int out_size)
{
    const float* x  = (const float*)d_in[0];
    const int*   ei = (const int*)d_in[1];

    const float *Wlin[3], *Wu[3], *cv[3], *bv[3], *bng[2], *bnb[2];
    if (in_sizes[6] == H * D * D) {
        for (int l = 0; l < 3; l++) {
            Wlin[l] = (const float*)d_in[2 + 4 * l];
            Wu[l]   = (const float*)d_in[3 + 4 * l];
            cv[l]   = (const float*)d_in[4 + 4 * l];
            bv[l]   = (const float*)d_in[5 + 4 * l];
        }
        bng[0] = (const float*)d_in[14]; bnb[0] = (const float*)d_in[15];
        bng[1] = (const float*)d_in[16]; bnb[1] = (const float*)d_in[17];
    } else {
        Wlin[0] = (const float*)d_in[2];  Wu[0] = (const float*)d_in[3];
        cv[0]   = (const float*)d_in[4];  bv[0] = (const float*)d_in[5];
        bng[0]  = (const float*)d_in[6];  bnb[0] = (const float*)d_in[7];
        Wlin[1] = (const float*)d_in[8];  Wu[1] = (const float*)d_in[9];
        cv[1]   = (const float*)d_in[10]; bv[1] = (const float*)d_in[11];
        bng[1]  = (const float*)d_in[12]; bnb[1] = (const float*)d_in[13];
        Wlin[2] = (const float*)d_in[14]; Wu[2] = (const float*)d_in[15];
        cv[2]   = (const float*)d_in[16]; bv[2] = (const float*)d_in[17];
    }

    float* out = (float*)d_out;
    float* t = nullptr;
    cudaGetSymbolAddress((void**)&t, g_t);

    const int SCGRID = (2 * NN + 7) / 8;

    // ---- layer 0 front (launch index 3 == mma_y for the ncu -s window) ----
    convertw3_kernel<<<(3 * HO * D + 255) / 256, 256>>>(Wlin[0], Wlin[1], Wlin[2]); // 0
    init_kernel<<<(NN + 255) / 256, 256>>>();                                       // 1
    convu_kernel<<<2500, 256>>>(x, Wu[0], -1, nullptr, nullptr);                    // 2
    launch_mma(0);                                                                  // 3 <- profiled
    count_kernel<<<(NE + 255) / 256, 256>>>(ei);
    scan_kernel<<<1, 1024>>>();
    fill_kernel<<<(NE + 255) / 256, 256>>>(ei);
    scatter_kernel<<<SCGRID, 256>>>(cv[0]);
    finalize_kernel<<<192, 256>>>(bv[0], t, 1, 0);

    // ---- layer 1 ----
    convu_kernel<<<2500, 256>>>(t, Wu[1], 0, bng[0], bnb[0]);
    launch_mma(1);
    scatter_kernel<<<SCGRID, 256>>>(cv[1]);
    finalize_kernel<<<192, 256>>>(bv[1], t, 1, 1);

    // ---- layer 2 -> d_out ----
    convu_kernel<<<2500, 256>>>(t, Wu[2], 1, bng[1], bnb[1]);
    launch_mma(2);
    scatter_kernel<<<SCGRID, 256>>>(cv[2]);
    finalize_kernel<<<192, 256>>>(bv[2], out, 0, -1);
}